// round 14
// baseline (speedup 1.0000x reference)
#include <cuda_runtime.h>
#include <cuda_bf16.h>
#include <cstdint>
#include <cstddef>

// Problem constants (fixed shapes).
#define BATCH 2
#define SEQ   2048
#define HID   2048
#define NH    16
#define HD    128
#define QKVN  (3*HID)   // 6144
#define MTOT  (BATCH*SEQ)

// Scratch (device globals; no allocations allowed).
__device__ __nv_bfloat16 g_ahi[(size_t)MTOT*HID];        // GEMM A hi (x, later ctx)
__device__ __nv_bfloat16 g_alo[(size_t)MTOT*HID];        // GEMM A lo
__device__ __nv_bfloat16 g_bhi[(size_t)QKVN*HID];        // weights^T hi [N][2048]
__device__ __nv_bfloat16 g_blo[(size_t)QKVN*HID];
__device__ __nv_bfloat16 g_qkvhi[(size_t)3*BATCH*NH*SEQ*HD];  // [which][b][h][s][d]
__device__ __nv_bfloat16 g_qkvlo[(size_t)3*BATCH*NH*SEQ*HD];

// ===========================================================================
// PTX helpers
// ===========================================================================
__device__ __forceinline__ unsigned smem_u32(const void* p) {
  unsigned a;
  asm("{ .reg .u64 t; cvta.to.shared.u64 t, %1; cvt.u32.u64 %0, t; }"
      : "=r"(a) : "l"(p));
  return a;
}
__device__ __forceinline__ void cp16(unsigned dst, const void* src) {
  asm volatile("cp.async.cg.shared.global [%0], [%1], 16;"
               :: "r"(dst), "l"(__cvta_generic_to_global(src)));
}
__device__ __forceinline__ void cp_commit() {
  asm volatile("cp.async.commit_group;" ::: "memory");
}
__device__ __forceinline__ void cp_wait0() {
  asm volatile("cp.async.wait_group 0;" ::: "memory");
}
__device__ __forceinline__ void cp_wait1() {
  asm volatile("cp.async.wait_group 1;" ::: "memory");
}
__device__ __forceinline__ void cp_wait3() {
  asm volatile("cp.async.wait_group 3;" ::: "memory");
}
__device__ __forceinline__ void ldsm4(unsigned* r, unsigned addr) {
  asm volatile("ldmatrix.sync.aligned.m8n8.x4.shared.b16 {%0,%1,%2,%3}, [%4];"
               : "=r"(r[0]), "=r"(r[1]), "=r"(r[2]), "=r"(r[3]) : "r"(addr));
}
__device__ __forceinline__ void ldsm4t(unsigned* r, unsigned addr) {
  asm volatile("ldmatrix.sync.aligned.m8n8.x4.trans.shared.b16 {%0,%1,%2,%3}, [%4];"
               : "=r"(r[0]), "=r"(r[1]), "=r"(r[2]), "=r"(r[3]) : "r"(addr));
}
__device__ __forceinline__ void mma_bf16(float* d, const unsigned* a,
                                         const unsigned* b) {
  asm volatile(
    "mma.sync.aligned.m16n8k16.row.col.f32.bf16.bf16.f32 "
    "{%0,%1,%2,%3}, {%4,%5,%6,%7}, {%8,%9}, {%0,%1,%2,%3};"
    : "+f"(d[0]), "+f"(d[1]), "+f"(d[2]), "+f"(d[3])
    : "r"(a[0]), "r"(a[1]), "r"(a[2]), "r"(a[3]), "r"(b[0]), "r"(b[1]));
}
__device__ __forceinline__ unsigned packbf(float lo, float hi) {
  unsigned r;
  asm("cvt.rn.bf16x2.f32 %0, %1, %2;" : "=r"(r) : "f"(hi), "f"(lo));
  return r;
}
__device__ __forceinline__ float blo(unsigned r) { return __int_as_float(r << 16); }
__device__ __forceinline__ float bhif(unsigned r) { return __int_as_float(r & 0xFFFF0000u); }

// ===========================================================================
// fp32 -> bf16 hi/lo split (elementwise) into g_ahi/g_alo
// ===========================================================================
__global__ void __launch_bounds__(256) k_split(const float4* __restrict__ in,
                                               int n4)
{
  int i = blockIdx.x * 256 + threadIdx.x;
  if (i >= n4) return;
  float4 v = in[i];
  __nv_bfloat16 h0 = __float2bfloat16(v.x), h1 = __float2bfloat16(v.y);
  __nv_bfloat16 h2 = __float2bfloat16(v.z), h3 = __float2bfloat16(v.w);
  __nv_bfloat16 l0 = __float2bfloat16(v.x - __bfloat162float(h0));
  __nv_bfloat16 l1 = __float2bfloat16(v.y - __bfloat162float(h1));
  __nv_bfloat16 l2 = __float2bfloat16(v.z - __bfloat162float(h2));
  __nv_bfloat16 l3 = __float2bfloat16(v.w - __bfloat162float(h3));
  __nv_bfloat162* hi = (__nv_bfloat162*)g_ahi;
  __nv_bfloat162* lo = (__nv_bfloat162*)g_alo;
  hi[2*i]   = __nv_bfloat162(h0, h1);
  hi[2*i+1] = __nv_bfloat162(h2, h3);
  lo[2*i]   = __nv_bfloat162(l0, l1);
  lo[2*i+1] = __nv_bfloat162(l2, l3);
}

// ===========================================================================
// w [K=2048][N] fp32 -> transposed hi/lo bf16 [N][2048] into g_bhi/g_blo
// ===========================================================================
__global__ void __launch_bounds__(256) k_splitT(const float* __restrict__ w,
                                                int N)
{
  __shared__ float t[32][33];
  const int n0 = blockIdx.x * 32, k0 = blockIdx.y * 32;
  const int tx = threadIdx.x & 31, ty = threadIdx.x >> 5;
#pragma unroll
  for (int i = 0; i < 4; ++i)
    t[ty + i*8][tx] = w[(size_t)(k0 + ty + i*8) * N + n0 + tx];
  __syncthreads();
#pragma unroll
  for (int i = 0; i < 4; ++i) {
    const int n = n0 + ty + i*8, k = k0 + tx;
    float v = t[tx][ty + i*8];
    __nv_bfloat16 h = __float2bfloat16(v);
    g_bhi[(size_t)n * HID + k] = h;
    g_blo[(size_t)n * HID + k] = __float2bfloat16(v - __bfloat162float(h));
  }
}

// ===========================================================================
// QKV GEMM: 64x128 CTA tile, 128 threads (4 warps, 32x64 warp tiles), KC=32,
// 2-stage cp.async, 3 CTAs/SM (61.4 KB smem) -> grid 3072 CTAs, ~1% tail.
// Epilogue: += bias, hi/lo split to g_qkvhi/lo in [which][b][h][s][d].
// ===========================================================================
#define KC 32
#define A64B 5120u                  // 64*80
#define B64B 10240u                 // 128*80
#define STG64 (2u*A64B + 2u*B64B)   // 30720
#define G64_SMEM (2u*STG64)         // 61440

__global__ void __launch_bounds__(128, 3) k_gemm_qkv(const float* __restrict__ bias)
{
  extern __shared__ __align__(128) char smem[];
  const unsigned sbase = smem_u32(smem);
  const int tid  = threadIdx.x;
  const int lane = tid & 31, wid = tid >> 5;
  const int m0 = blockIdx.y * 64, n0 = blockIdx.x * 128;
  const int K = HID, N = QKVN;
  const int NC = K / KC;            // 64

  auto load_chunk = [&](int c) {
    const unsigned st = sbase + (unsigned)(c & 1) * STG64;
    const int koff = c * KC;
#pragma unroll
    for (int i = 0; i < 12; ++i) {
      const int q = tid + i * 128;     // 1536 16B segs
      unsigned dstoff; const __nv_bfloat16* src;
      if (q < 512) {                   // A hi/lo: 64 rows x 4 segs each
        const int mat = q >> 8, idx = q & 255, row = idx >> 2, seg = idx & 3;
        dstoff = (unsigned)mat * A64B + (unsigned)row * 80u + (unsigned)seg * 16u;
        src = (mat ? g_alo : g_ahi) + (size_t)(m0 + row) * K + koff + seg * 8;
      } else {                         // B hi/lo: 128 rows x 4 segs each
        const int qq = q - 512, mat = qq >> 9, idx = qq & 511;
        const int row = idx >> 2, seg = idx & 3;
        dstoff = 2u*A64B + (unsigned)mat * B64B
               + (unsigned)row * 80u + (unsigned)seg * 16u;
        src = (mat ? g_blo : g_bhi) + (size_t)(n0 + row) * K + koff + seg * 8;
      }
      cp16(st + dstoff, src);
    }
  };

  // Warp tiling: wm in {0,1} -> 32 M rows; wn in {0,1} -> 64 N cols.
  const int wm = wid & 1, wn = wid >> 1;
  const unsigned aoff0 = (unsigned)(wm*32 + (lane & 15)) * 80u
                       + (unsigned)(lane >> 4) * 16u;
  const unsigned boff0 = 2u*A64B
                       + (unsigned)(wn*64 + (lane & 7) + ((lane >> 4) << 3)) * 80u
                       + (unsigned)((lane >> 3) & 1) * 16u;

  float acc[2][8][4];
#pragma unroll
  for (int mi = 0; mi < 2; ++mi)
#pragma unroll
    for (int nt = 0; nt < 8; ++nt)
#pragma unroll
      for (int r = 0; r < 4; ++r) acc[mi][nt][r] = 0.f;

  load_chunk(0); cp_commit();

  for (int c = 0; c < NC; ++c) {
    if (c + 1 < NC) load_chunk(c + 1);
    cp_commit();
    cp_wait1();
    __syncthreads();

    const unsigned st = sbase + (unsigned)(c & 1) * STG64;
#pragma unroll
    for (int ks = 0; ks < 2; ++ks) {
      unsigned ah[2][4], al[2][4];
#pragma unroll
      for (int mi = 0; mi < 2; ++mi) {
        const unsigned a = st + aoff0 + (unsigned)mi*1280u + (unsigned)ks*32u;
        ldsm4(ah[mi], a);
        ldsm4(al[mi], a + A64B);
      }
#pragma unroll
      for (int nj = 0; nj < 4; ++nj) {
        unsigned bh[4], bl[4];
        const unsigned b = st + boff0 + (unsigned)nj*1280u + (unsigned)ks*32u;
        ldsm4(bh, b);
        ldsm4(bl, b + B64B);
#pragma unroll
        for (int mi = 0; mi < 2; ++mi)
#pragma unroll
          for (int hf = 0; hf < 2; ++hf) {
            float* a = acc[mi][nj*2 + hf];
            mma_bf16(a, ah[mi], &bh[hf*2]);
            mma_bf16(a, ah[mi], &bl[hf*2]);
            mma_bf16(a, al[mi], &bh[hf*2]);
          }
      }
    }
    __syncthreads();
  }

  // Epilogue: bias + split-store to head-major q/k/v.
#pragma unroll
  for (int mi = 0; mi < 2; ++mi)
#pragma unroll
    for (int nt = 0; nt < 8; ++nt) {
      const int r0 = m0 + wm*32 + mi*16 + (lane >> 2);
      const int n  = n0 + wn*64 + nt*8 + (lane & 3)*2;
      const float2 bv = *(const float2*)&bias[n];
      const float p0 = acc[mi][nt][0] + bv.x, p1 = acc[mi][nt][1] + bv.y;
      const float p2 = acc[mi][nt][2] + bv.x, p3 = acc[mi][nt][3] + bv.y;
      const int which = n >> 11, hh = (n >> 7) & 15, dd = n & 127;
      const int bb = r0 >> 11, s = r0 & 2047;
      const size_t o0 = ((size_t)((which*BATCH + bb)*NH + hh) * SEQ + s) * HD + dd;
      const size_t o1 = o0 + 8*HD;
      const unsigned h0 = packbf(p0, p1);
      const unsigned l0 = packbf(p0 - blo(h0), p1 - bhif(h0));
      const unsigned h1 = packbf(p2, p3);
      const unsigned l1 = packbf(p2 - blo(h1), p3 - bhif(h1));
      *(unsigned*)&g_qkvhi[o0] = h0;  *(unsigned*)&g_qkvlo[o0] = l0;
      *(unsigned*)&g_qkvhi[o1] = h1;  *(unsigned*)&g_qkvlo[o1] = l1;
      (void)N;
    }
}

// ===========================================================================
// Proj GEMM (R12 kernel): 128x128 CTA tile, 256 threads, 2 CTAs/SM.
// ===========================================================================
#define MATB 10240u                 // 128*80
#define STAGEB (4u*MATB)            // 40960
#define G_SMEM (2u*STAGEB)          // 81920

__global__ void __launch_bounds__(256, 2) k_gemm_o(float* __restrict__ Carg)
{
  extern __shared__ __align__(128) char smem[];
  const unsigned sbase = smem_u32(smem);
  const int tid  = threadIdx.x;
  const int lane = tid & 31, wid = tid >> 5;
  const int m0 = blockIdx.y * 128, n0 = blockIdx.x * 128;
  const int K = HID, N = HID;
  const int NC = K / KC;            // 64

  auto load_chunk = [&](int c) {
    const int koff = c * KC;
#pragma unroll
    for (int i = 0; i < 8; ++i) {
      const int q   = tid + i * 256;
      const int mat = q >> 9, idx = q & 511, row = idx >> 2, seg = idx & 3;
      const __nv_bfloat16* base =
        (mat == 0) ? g_ahi : (mat == 1) ? g_alo : (mat == 2) ? g_bhi : g_blo;
      const int grow = ((mat < 2) ? m0 : n0) + row;
      cp16(sbase + (unsigned)(c & 1) * STAGEB + (unsigned)mat * MATB
               + (unsigned)row * 80u + (unsigned)seg * 16u,
           base + (size_t)grow * K + koff + seg * 8);
    }
  };

  const int wm = wid & 3, wn = wid >> 2;
  const unsigned aoff0 = (unsigned)(wm*32 + (lane & 15)) * 80u
                       + (unsigned)(lane >> 4) * 16u;
  const unsigned boff0 = 2u*MATB
                       + (unsigned)(wn*64 + (lane & 7) + ((lane >> 4) << 3)) * 80u
                       + (unsigned)((lane >> 3) & 1) * 16u;

  float acc[2][8][4];
#pragma unroll
  for (int mi = 0; mi < 2; ++mi)
#pragma unroll
    for (int nt = 0; nt < 8; ++nt)
#pragma unroll
      for (int r = 0; r < 4; ++r) acc[mi][nt][r] = 0.f;

  load_chunk(0); cp_commit();

  for (int c = 0; c < NC; ++c) {
    if (c + 1 < NC) load_chunk(c + 1);
    cp_commit();
    cp_wait1();
    __syncthreads();

    const unsigned st = sbase + (unsigned)(c & 1) * STAGEB;
#pragma unroll
    for (int ks = 0; ks < 2; ++ks) {
      unsigned ah[2][4], al[2][4];
#pragma unroll
      for (int mi = 0; mi < 2; ++mi) {
        const unsigned a = st + aoff0 + (unsigned)mi*1280u + (unsigned)ks*32u;
        ldsm4(ah[mi], a);
        ldsm4(al[mi], a + MATB);
      }
#pragma unroll
      for (int nj = 0; nj < 4; ++nj) {
        unsigned bh[4], bl[4];
        const unsigned b = st + boff0 + (unsigned)nj*1280u + (unsigned)ks*32u;
        ldsm4(bh, b);
        ldsm4(bl, b + MATB);
#pragma unroll
        for (int mi = 0; mi < 2; ++mi)
#pragma unroll
          for (int hf = 0; hf < 2; ++hf) {
            float* a = acc[mi][nj*2 + hf];
            mma_bf16(a, ah[mi], &bh[hf*2]);
            mma_bf16(a, ah[mi], &bl[hf*2]);
            mma_bf16(a, al[mi], &bh[hf*2]);
          }
      }
    }
    __syncthreads();
  }

#pragma unroll
  for (int mi = 0; mi < 2; ++mi)
#pragma unroll
    for (int nt = 0; nt < 8; ++nt) {
      const int r0 = m0 + wm*32 + mi*16 + (lane >> 2);
      const int n  = n0 + wn*64 + nt*8 + (lane & 3)*2;
      *(float2*)&Carg[(size_t)r0 * N + n] =
          make_float2(acc[mi][nt][0], acc[mi][nt][1]);
      *(float2*)&Carg[(size_t)(r0 + 8) * N + n] =
          make_float2(acc[mi][nt][2], acc[mi][nt][3]);
    }
}

// ===========================================================================
// Pipelined HMMA flash attention (causal). 256 threads, q-tile 128, k-tile 64.
// Iteration kt: issue S_next = Q*K(kt+1) MMAs FIRST, then softmax(S_cur) runs
// on ALU/MUFU while they are in flight, then PV(kt). K and V staged separately
// so K(kt+2) can prefetch from the iteration top (its slot region is dead).
// One wait_group(1) + one barrier guarantees {V(kt), K(kt+1)} resident while
// V(kt+1) keeps prefetching; final iteration uses wait_group(0).
// Q hi and lo both persistent in smem (frees regs for S double-buffer).
// ===========================================================================
#define AT_STR   272u                 // bytes per 128-col bf16 row (+pad)
#define AT_MATB  17408u               // 64*272   (one K or V matrix)
#define AT_KVST  (4u*AT_MATB)         // 69632    (Khi|Klo|Vhi|Vlo)
#define AT_QHI   (2u*AT_KVST)         // 139264
#define AT_QLO   (AT_QHI + 34816u)    // 174080
#define AT_SMEM  (AT_QLO + 34816u)    // 208896

__global__ void __launch_bounds__(256, 1) k_attn()
{
  extern __shared__ __align__(128) char smem[];
  const unsigned sb = smem_u32(smem);
  const int tid = threadIdx.x, lane = tid & 31, w = tid >> 5;
  const int qt = (int)gridDim.x - 1 - (int)blockIdx.x;   // heavy tiles first
  const int h = blockIdx.y, b = blockIdx.z;
  const int q0 = qt * 128;
  const int ktmax = 2*qt + 1;

  const size_t offQ = ((size_t)((0*BATCH + b)*NH + h)) * SEQ * HD;
  const size_t offK = ((size_t)((1*BATCH + b)*NH + h)) * SEQ * HD;
  const size_t offV = ((size_t)((2*BATCH + b)*NH + h)) * SEQ * HD;

  auto stage_k = [&](int kt) {
    const int k0 = kt * 64;
    const unsigned st = sb + (unsigned)(kt & 1) * AT_KVST;
#pragma unroll
    for (int i = 0; i < 8; ++i) {
      const int q = tid + i * 256;            // 2048 segs (K hi+lo)
      const int mat = q >> 10, row = (q >> 4) & 63, seg = q & 15;
      cp16(st + (unsigned)mat * AT_MATB + (unsigned)row * AT_STR + (unsigned)seg * 16u,
           (mat ? g_qkvlo : g_qkvhi) + offK + (size_t)(k0 + row) * HD + seg * 8);
    }
  };
  auto stage_v = [&](int kt) {
    const int k0 = kt * 64;
    const unsigned st = sb + (unsigned)(kt & 1) * AT_KVST + 2u*AT_MATB;
#pragma unroll
    for (int i = 0; i < 8; ++i) {
      const int q = tid + i * 256;            // 2048 segs (V hi+lo)
      const int mat = q >> 10, row = (q >> 4) & 63, seg = q & 15;
      cp16(st + (unsigned)mat * AT_MATB + (unsigned)row * AT_STR + (unsigned)seg * 16u,
           (mat ? g_qkvlo : g_qkvhi) + offV + (size_t)(k0 + row) * HD + seg * 8);
    }
  };

  // Stage Q (hi+lo) into persistent blocks.
#pragma unroll
  for (int i = 0; i < 16; ++i) {
    const int q = tid + i * 256;              // 4096 segs
    const int mat = q >> 11, row = (q >> 4) & 127, seg = q & 15;
    cp16(sb + (mat ? AT_QLO : AT_QHI)
            + (unsigned)row * AT_STR + (unsigned)seg * 16u,
         (mat ? g_qkvlo : g_qkvhi) + offQ + (size_t)(q0 + row) * HD + seg * 8);
  }
  cp_commit();                                // G: Q
  stage_k(0); cp_commit();                    // G: K0
  stage_v(0); cp_commit();                    // G: V0
  stage_k(1); cp_commit();                    // G: K1
  stage_v(1); cp_commit();                    // G: V1

  // ldmatrix per-lane offsets
  const unsigned aoff = (unsigned)(w*16 + (lane & 15)) * AT_STR
                      + (unsigned)(lane >> 4) * 16u;                 // Q rows
  const unsigned boff = (unsigned)((lane & 7) + ((lane >> 4) << 3)) * AT_STR
                      + (unsigned)((lane >> 3) & 1) * 16u;           // K cols
  const unsigned voff = (unsigned)(lane & 15) * AT_STR
                      + (unsigned)(lane >> 4) * 16u;                 // V (trans)

  // S = Q K^T (3-term) for the K tile at slot base stK.
  auto compute_S = [&](unsigned stK, float S[8][4]) {
#pragma unroll
    for (int nb = 0; nb < 8; ++nb)
#pragma unroll
      for (int r = 0; r < 4; ++r) S[nb][r] = 0.f;
#pragma unroll
    for (int kc = 0; kc < 8; ++kc) {
      unsigned qhr[4], qlr[4];
      ldsm4(qhr, sb + AT_QHI + aoff + (unsigned)kc*32u);
      ldsm4(qlr, sb + AT_QLO + aoff + (unsigned)kc*32u);
#pragma unroll
      for (int j = 0; j < 4; ++j) {
        unsigned kh[4], kl[4];
        const unsigned bo = boff + (unsigned)j*4352u + (unsigned)kc*32u;
        ldsm4(kh, stK + bo);
        ldsm4(kl, stK + AT_MATB + bo);
        mma_bf16(S[2*j],   qhr, &kh[0]);  mma_bf16(S[2*j+1], qhr, &kh[2]);
        mma_bf16(S[2*j],   qhr, &kl[0]);  mma_bf16(S[2*j+1], qhr, &kl[2]);
        mma_bf16(S[2*j],   qlr, &kh[0]);  mma_bf16(S[2*j+1], qlr, &kh[2]);
      }
    }
  };

  const float sc = 0.08838834764831845f;   // 1/sqrt(128)
  float m0r = -1e30f, m1r = -1e30f, l0 = 0.f, l1 = 0.f;
  float O[16][4];
#pragma unroll
  for (int nb = 0; nb < 16; ++nb)
#pragma unroll
    for (int r = 0; r < 4; ++r) O[nb][r] = 0.f;

  const int wrow = q0 + w*16;              // warp's first q row

  // Pre-loop: wait {Q, K0}; compute S_0.
  cp_wait3();
  __syncthreads();
  float Scur[8][4];
  compute_S(sb, Scur);

  for (int kt = 0; kt <= ktmax; ++kt) {
    // {V(kt), K(kt+1)} resident after this; V(kt+1)/K(kt+2) may fly.
    if (kt == ktmax) cp_wait0(); else cp_wait1();
    __syncthreads();

    if (kt + 2 <= ktmax) stage_k(kt + 2);    // K slot region dead since iter kt-1
    cp_commit();

    // Issue next tile's S MMAs first; softmax below overlaps them.
    float Snext[8][4];
    const bool have_next = (kt < ktmax) && ((kt + 1) * 64 <= wrow + 15);
    if (have_next)
      compute_S(sb + (unsigned)((kt + 1) & 1) * AT_KVST, Snext);

    const int k0 = kt * 64;
    const unsigned st = sb + (unsigned)(kt & 1) * AT_KVST;
    if (k0 <= wrow + 15) {
      // ---- causal mask (only near the diagonal) ----
      if (k0 + 63 > wrow) {
        const int rl0 = wrow + (lane >> 2), rl1 = rl0 + 8;
#pragma unroll
        for (int nb = 0; nb < 8; ++nb) {
          const int c0 = k0 + nb*8 + 2*(lane & 3), c1 = c0 + 1;
          if (c0 > rl0) Scur[nb][0] = -1e30f;
          if (c1 > rl0) Scur[nb][1] = -1e30f;
          if (c0 > rl1) Scur[nb][2] = -1e30f;
          if (c1 > rl1) Scur[nb][3] = -1e30f;
        }
      }

      // ---- online softmax ----
      float mx0 = -1e30f, mx1 = -1e30f;
#pragma unroll
      for (int nb = 0; nb < 8; ++nb) {
        mx0 = fmaxf(mx0, fmaxf(Scur[nb][0], Scur[nb][1]));
        mx1 = fmaxf(mx1, fmaxf(Scur[nb][2], Scur[nb][3]));
      }
      mx0 = fmaxf(mx0, __shfl_xor_sync(0xFFFFFFFFu, mx0, 1));
      mx0 = fmaxf(mx0, __shfl_xor_sync(0xFFFFFFFFu, mx0, 2));
      mx1 = fmaxf(mx1, __shfl_xor_sync(0xFFFFFFFFu, mx1, 1));
      mx1 = fmaxf(mx1, __shfl_xor_sync(0xFFFFFFFFu, mx1, 2));
      const float mn0 = fmaxf(m0r, mx0), mn1 = fmaxf(m1r, mx1);
      const float a0 = __expf(sc * (m0r - mn0));
      const float a1 = __expf(sc * (m1r - mn1));
      m0r = mn0; m1r = mn1;

      float ls0 = 0.f, ls1 = 0.f;
#pragma unroll
      for (int nb = 0; nb < 8; ++nb) {
        Scur[nb][0] = __expf(sc * (Scur[nb][0] - mn0));
        Scur[nb][1] = __expf(sc * (Scur[nb][1] - mn0));
        Scur[nb][2] = __expf(sc * (Scur[nb][2] - mn1));
        Scur[nb][3] = __expf(sc * (Scur[nb][3] - mn1));
        ls0 += Scur[nb][0] + Scur[nb][1];
        ls1 += Scur[nb][2] + Scur[nb][3];
      }
      l0 = l0 * a0 + ls0;
      l1 = l1 * a1 + ls1;

#pragma unroll
      for (int nb = 0; nb < 16; ++nb) {
        O[nb][0] *= a0; O[nb][1] *= a0;
        O[nb][2] *= a1; O[nb][3] *= a1;
      }

      // ---- P hi/lo fragments ----
      unsigned ph[4][4], pl[4][4];
#pragma unroll
      for (int kc2 = 0; kc2 < 4; ++kc2) {
        const float* p0 = Scur[2*kc2];
        const float* p1 = Scur[2*kc2+1];
        ph[kc2][0] = packbf(p0[0], p0[1]);
        ph[kc2][1] = packbf(p0[2], p0[3]);
        ph[kc2][2] = packbf(p1[0], p1[1]);
        ph[kc2][3] = packbf(p1[2], p1[3]);
        pl[kc2][0] = packbf(p0[0] - blo(ph[kc2][0]), p0[1] - bhif(ph[kc2][0]));
        pl[kc2][1] = packbf(p0[2] - blo(ph[kc2][1]), p0[3] - bhif(ph[kc2][1]));
        pl[kc2][2] = packbf(p1[0] - blo(ph[kc2][2]), p1[1] - bhif(ph[kc2][2]));
        pl[kc2][3] = packbf(p1[2] - blo(ph[kc2][3]), p1[3] - bhif(ph[kc2][3]));
      }

      // ---- O += P V (3-term), 16x128 ----
#pragma unroll
      for (int kc2 = 0; kc2 < 4; ++kc2) {
#pragma unroll
        for (int j = 0; j < 8; ++j) {
          unsigned vh[4], vl[4];
          const unsigned vo = voff + (unsigned)kc2*4352u + (unsigned)j*32u;
          ldsm4t(vh, st + 2*AT_MATB + vo);
          ldsm4t(vl, st + 3*AT_MATB + vo);
          mma_bf16(O[2*j],   ph[kc2], &vh[0]);  mma_bf16(O[2*j+1], ph[kc2], &vh[2]);
          mma_bf16(O[2*j],   ph[kc2], &vl[0]);  mma_bf16(O[2*j+1], ph[kc2], &vl[2]);
          mma_bf16(O[2*j],   pl[kc2], &vh[0]);  mma_bf16(O[2*j+1], pl[kc2], &vh[2]);
        }
      }
    }

    __syncthreads();       // all warps done with V(kt) before restage
    if (kt + 2 <= ktmax) stage_v(kt + 2);
    cp_commit();

    if (have_next) {
#pragma unroll
      for (int nb = 0; nb < 8; ++nb)
#pragma unroll
        for (int r = 0; r < 4; ++r) Scur[nb][r] = Snext[nb][r];
    }
  }

  // ---- finalize ----
  l0 += __shfl_xor_sync(0xFFFFFFFFu, l0, 1);
  l0 += __shfl_xor_sync(0xFFFFFFFFu, l0, 2);
  l1 += __shfl_xor_sync(0xFFFFFFFFu, l1, 1);
  l1 += __shfl_xor_sync(0xFFFFFFFFu, l1, 2);
  const float inv0 = 1.f / l0, inv1 = 1.f / l1;

  const int s0 = q0 + w*16 + (lane >> 2), s1 = s0 + 8;
  const size_t rb0 = ((size_t)b*SEQ + s0) * HID + h*HD;
  const size_t rb1 = ((size_t)b*SEQ + s1) * HID + h*HD;
#pragma unroll
  for (int nb = 0; nb < 16; ++nb) {
    const int c = nb*8 + 2*(lane & 3);
    const float v0 = O[nb][0]*inv0, v1 = O[nb][1]*inv0;
    const float v2 = O[nb][2]*inv1, v3 = O[nb][3]*inv1;
    const unsigned h0 = packbf(v0, v1);
    const unsigned lo0 = packbf(v0 - blo(h0), v1 - bhif(h0));
    const unsigned h1 = packbf(v2, v3);
    const unsigned lo1 = packbf(v2 - blo(h1), v3 - bhif(h1));
    *(unsigned*)&g_ahi[rb0 + c] = h0;  *(unsigned*)&g_alo[rb0 + c] = lo0;
    *(unsigned*)&g_ahi[rb1 + c] = h1;  *(unsigned*)&g_alo[rb1 + c] = lo1;
  }
}

// ---------------------------------------------------------------------------
extern "C" void kernel_launch(void* const* d_in, const int* in_sizes, int n_in,
                              void* d_out, int out_size)
{
  const float* x     = (const float*)d_in[0];
  const float* w_qkv = (const float*)d_in[1];
  const float* b_qkv = (const float*)d_in[2];
  const float* w_o   = (const float*)d_in[3];
  float* out = (float*)d_out;

  cudaFuncSetAttribute(k_gemm_qkv, cudaFuncAttributeMaxDynamicSharedMemorySize, G64_SMEM);
  cudaFuncSetAttribute(k_gemm_o,   cudaFuncAttributeMaxDynamicSharedMemorySize, G_SMEM);
  cudaFuncSetAttribute(k_attn,     cudaFuncAttributeMaxDynamicSharedMemorySize, AT_SMEM);

  const int n4x = MTOT*HID/4;   // 2,097,152

  // 1) split x; transpose+split w_qkv
  k_split<<<(n4x + 255)/256, 256>>>((const float4*)x, n4x);
  k_splitT<<<dim3(QKVN/32, HID/32), 256>>>(w_qkv, QKVN);
  // 2) QKV GEMM (64x128 tiles, 3 CTAs/SM) -> head-major bf16 hi/lo q/k/v
  k_gemm_qkv<<<dim3(QKVN/128, MTOT/64), 128, G64_SMEM>>>(b_qkv);
  // 3) pipelined HMMA flash attention -> ctx hi/lo into GEMM A buffers
  k_attn<<<dim3(SEQ/128, NH, BATCH), 256, AT_SMEM>>>();
  // 4) transpose+split w_o
  k_splitT<<<dim3(HID/32, HID/32), 256>>>(w_o, HID);
  // 5) output projection -> d_out
  k_gemm_o<<<dim3(HID/128, MTOT/128), 256, G_SMEM>>>(out);
}

// round 15
// speedup vs baseline: 1.2434x; 1.2434x over previous
#include <cuda_runtime.h>
#include <cuda_bf16.h>
#include <cuda_fp16.h>
#include <cstdint>
#include <cstddef>

// Problem constants (fixed shapes).
#define BATCH 2
#define SEQ   2048
#define HID   2048
#define NH    16
#define HD    128
#define QKVN  (3*HID)   // 6144
#define MTOT  (BATCH*SEQ)

// Scratch (device globals; no allocations allowed). Byte-compatible buffers,
// reinterpreted as __half where the fp16 GEMM path uses them.
__device__ __nv_bfloat16 g_ahi[(size_t)MTOT*HID];        // fp16 A (x, later ctx)
__device__ __nv_bfloat16 g_alo[(size_t)MTOT*HID];        // (unused by fp16 path)
__device__ __nv_bfloat16 g_bhi[(size_t)QKVN*HID];        // fp16 weights^T hi [N][2048]
__device__ __nv_bfloat16 g_blo[(size_t)QKVN*HID];        // fp16 weights^T lo
__device__ __nv_bfloat16 g_qkvhi[(size_t)3*BATCH*NH*SEQ*HD];  // bf16 [which][b][h][s][d]
__device__ __nv_bfloat16 g_qkvlo[(size_t)3*BATCH*NH*SEQ*HD];

// ===========================================================================
// PTX helpers
// ===========================================================================
__device__ __forceinline__ unsigned smem_u32(const void* p) {
  unsigned a;
  asm("{ .reg .u64 t; cvta.to.shared.u64 t, %1; cvt.u32.u64 %0, t; }"
      : "=r"(a) : "l"(p));
  return a;
}
__device__ __forceinline__ void cp16(unsigned dst, const void* src) {
  asm volatile("cp.async.cg.shared.global [%0], [%1], 16;"
               :: "r"(dst), "l"(__cvta_generic_to_global(src)));
}
__device__ __forceinline__ void cp_commit() {
  asm volatile("cp.async.commit_group;" ::: "memory");
}
__device__ __forceinline__ void cp_wait0() {
  asm volatile("cp.async.wait_group 0;" ::: "memory");
}
__device__ __forceinline__ void cp_wait1() {
  asm volatile("cp.async.wait_group 1;" ::: "memory");
}
__device__ __forceinline__ void cp_wait3() {
  asm volatile("cp.async.wait_group 3;" ::: "memory");
}
__device__ __forceinline__ void ldsm4(unsigned* r, unsigned addr) {
  asm volatile("ldmatrix.sync.aligned.m8n8.x4.shared.b16 {%0,%1,%2,%3}, [%4];"
               : "=r"(r[0]), "=r"(r[1]), "=r"(r[2]), "=r"(r[3]) : "r"(addr));
}
__device__ __forceinline__ void ldsm4t(unsigned* r, unsigned addr) {
  asm volatile("ldmatrix.sync.aligned.m8n8.x4.trans.shared.b16 {%0,%1,%2,%3}, [%4];"
               : "=r"(r[0]), "=r"(r[1]), "=r"(r[2]), "=r"(r[3]) : "r"(addr));
}
__device__ __forceinline__ void mma_bf16(float* d, const unsigned* a,
                                         const unsigned* b) {
  asm volatile(
    "mma.sync.aligned.m16n8k16.row.col.f32.bf16.bf16.f32 "
    "{%0,%1,%2,%3}, {%4,%5,%6,%7}, {%8,%9}, {%0,%1,%2,%3};"
    : "+f"(d[0]), "+f"(d[1]), "+f"(d[2]), "+f"(d[3])
    : "r"(a[0]), "r"(a[1]), "r"(a[2]), "r"(a[3]), "r"(b[0]), "r"(b[1]));
}
__device__ __forceinline__ void mma_f16(float* d, const unsigned* a,
                                        const unsigned* b) {
  asm volatile(
    "mma.sync.aligned.m16n8k16.row.col.f32.f16.f16.f32 "
    "{%0,%1,%2,%3}, {%4,%5,%6,%7}, {%8,%9}, {%0,%1,%2,%3};"
    : "+f"(d[0]), "+f"(d[1]), "+f"(d[2]), "+f"(d[3])
    : "r"(a[0]), "r"(a[1]), "r"(a[2]), "r"(a[3]), "r"(b[0]), "r"(b[1]));
}
__device__ __forceinline__ unsigned packbf(float lo, float hi) {
  unsigned r;
  asm("cvt.rn.bf16x2.f32 %0, %1, %2;" : "=r"(r) : "f"(hi), "f"(lo));
  return r;
}
__device__ __forceinline__ unsigned packf16(float lo, float hi) {
  unsigned r;
  asm("cvt.rn.f16x2.f32 %0, %1, %2;" : "=r"(r) : "f"(hi), "f"(lo));
  return r;
}
__device__ __forceinline__ float blo(unsigned r) { return __int_as_float(r << 16); }
__device__ __forceinline__ float bhif(unsigned r) { return __int_as_float(r & 0xFFFF0000u); }

// ===========================================================================
// fp32 -> fp16 convert (elementwise) into g_ahi (as __half)
// ===========================================================================
__global__ void __launch_bounds__(256) k_split(const float4* __restrict__ in,
                                               int n4)
{
  int i = blockIdx.x * 256 + threadIdx.x;
  if (i >= n4) return;
  float4 v = in[i];
  __half2* o = (__half2*)g_ahi;
  o[2*i]   = __floats2half2_rn(v.x, v.y);
  o[2*i+1] = __floats2half2_rn(v.z, v.w);
}

// ===========================================================================
// w [K=2048][N] fp32 -> transposed fp16 hi/lo [N][2048] into g_bhi/g_blo
// ===========================================================================
__global__ void __launch_bounds__(256) k_splitT(const float* __restrict__ w,
                                                int N)
{
  __shared__ float t[32][33];
  const int n0 = blockIdx.x * 32, k0 = blockIdx.y * 32;
  const int tx = threadIdx.x & 31, ty = threadIdx.x >> 5;
#pragma unroll
  for (int i = 0; i < 4; ++i)
    t[ty + i*8][tx] = w[(size_t)(k0 + ty + i*8) * N + n0 + tx];
  __syncthreads();
#pragma unroll
  for (int i = 0; i < 4; ++i) {
    const int n = n0 + ty + i*8, k = k0 + tx;
    float v = t[tx][ty + i*8];
    __half h = __float2half_rn(v);
    ((__half*)g_bhi)[(size_t)n * HID + k] = h;
    ((__half*)g_blo)[(size_t)n * HID + k] = __float2half_rn(v - __half2float(h));
  }
}

// ===========================================================================
// QKV GEMM (fp16 2-term): C = A_f16[M,2048] @ (Whi+Wlo)^T[N,2048] + bias.
// 64x128 CTA tile, 128 threads (4 warps, 32x64 warp tiles), KC=32,
// 2-stage cp.async, 3 CTAs/SM. Epilogue: bf16 hi/lo split to g_qkvhi/lo.
// ===========================================================================
#define KC 32
#define QA_MATB 5120u                // 64*80
#define QB_MATB 10240u               // 128*80
#define QSTG (QA_MATB + 2u*QB_MATB)  // 25600
#define GQ_SMEM (2u*QSTG)            // 51200

__global__ void __launch_bounds__(128, 3) k_gemm_qkv(const float* __restrict__ bias)
{
  extern __shared__ __align__(128) char smem[];
  const unsigned sbase = smem_u32(smem);
  const int tid  = threadIdx.x;
  const int lane = tid & 31, wid = tid >> 5;
  const int m0 = blockIdx.y * 64, n0 = blockIdx.x * 128;
  const int K = HID;
  const int NC = K / KC;            // 64
  const __half* Af  = (const __half*)g_ahi;
  const __half* Bh  = (const __half*)g_bhi;
  const __half* Bl  = (const __half*)g_blo;

  auto load_chunk = [&](int c) {
    const unsigned st = sbase + (unsigned)(c & 1) * QSTG;
    const int koff = c * KC;
#pragma unroll
    for (int i = 0; i < 10; ++i) {
      const int q = tid + i * 128;     // 1280 16B segs
      unsigned dstoff; const __half* src;
      if (q < 256) {                   // A: 64 rows x 4 segs
        const int row = q >> 2, seg = q & 3;
        dstoff = (unsigned)row * 80u + (unsigned)seg * 16u;
        src = Af + (size_t)(m0 + row) * K + koff + seg * 8;
      } else {                         // B hi/lo: 128 rows x 4 segs each
        const int qq = q - 256, mat = qq >> 9, idx = qq & 511;
        const int row = idx >> 2, seg = idx & 3;
        dstoff = QA_MATB + (unsigned)mat * QB_MATB
               + (unsigned)row * 80u + (unsigned)seg * 16u;
        src = (mat ? Bl : Bh) + (size_t)(n0 + row) * K + koff + seg * 8;
      }
      cp16(st + dstoff, src);
    }
  };

  // Warp tiling: wm in {0,1} -> 32 M rows; wn in {0,1} -> 64 N cols.
  const int wm = wid & 1, wn = wid >> 1;
  const unsigned aoff0 = (unsigned)(wm*32 + (lane & 15)) * 80u
                       + (unsigned)(lane >> 4) * 16u;
  const unsigned boff0 = QA_MATB
                       + (unsigned)(wn*64 + (lane & 7) + ((lane >> 4) << 3)) * 80u
                       + (unsigned)((lane >> 3) & 1) * 16u;

  float acc[2][8][4];
#pragma unroll
  for (int mi = 0; mi < 2; ++mi)
#pragma unroll
    for (int nt = 0; nt < 8; ++nt)
#pragma unroll
      for (int r = 0; r < 4; ++r) acc[mi][nt][r] = 0.f;

  load_chunk(0); cp_commit();

  for (int c = 0; c < NC; ++c) {
    if (c + 1 < NC) load_chunk(c + 1);
    cp_commit();
    cp_wait1();
    __syncthreads();

    const unsigned st = sbase + (unsigned)(c & 1) * QSTG;
#pragma unroll
    for (int ks = 0; ks < 2; ++ks) {
      unsigned ah[2][4];
#pragma unroll
      for (int mi = 0; mi < 2; ++mi)
        ldsm4(ah[mi], st + aoff0 + (unsigned)mi*1280u + (unsigned)ks*32u);
#pragma unroll
      for (int nj = 0; nj < 4; ++nj) {
        unsigned bh[4], bl[4];
        const unsigned b = st + boff0 + (unsigned)nj*1280u + (unsigned)ks*32u;
        ldsm4(bh, b);
        ldsm4(bl, b + QB_MATB);
#pragma unroll
        for (int mi = 0; mi < 2; ++mi)
#pragma unroll
          for (int hf = 0; hf < 2; ++hf) {
            float* a = acc[mi][nj*2 + hf];
            mma_f16(a, ah[mi], &bh[hf*2]);
            mma_f16(a, ah[mi], &bl[hf*2]);
          }
      }
    }
    __syncthreads();
  }

  // Epilogue: bias + bf16 hi/lo split-store to head-major q/k/v.
#pragma unroll
  for (int mi = 0; mi < 2; ++mi)
#pragma unroll
    for (int nt = 0; nt < 8; ++nt) {
      const int r0 = m0 + wm*32 + mi*16 + (lane >> 2);
      const int n  = n0 + wn*64 + nt*8 + (lane & 3)*2;
      const float2 bv = *(const float2*)&bias[n];
      const float p0 = acc[mi][nt][0] + bv.x, p1 = acc[mi][nt][1] + bv.y;
      const float p2 = acc[mi][nt][2] + bv.x, p3 = acc[mi][nt][3] + bv.y;
      const int which = n >> 11, hh = (n >> 7) & 15, dd = n & 127;
      const int bb = r0 >> 11, s = r0 & 2047;
      const size_t o0 = ((size_t)((which*BATCH + bb)*NH + hh) * SEQ + s) * HD + dd;
      const size_t o1 = o0 + 8*HD;
      const unsigned h0 = packbf(p0, p1);
      const unsigned l0 = packbf(p0 - blo(h0), p1 - bhif(h0));
      const unsigned h1 = packbf(p2, p3);
      const unsigned l1 = packbf(p2 - blo(h1), p3 - bhif(h1));
      *(unsigned*)&g_qkvhi[o0] = h0;  *(unsigned*)&g_qkvlo[o0] = l0;
      *(unsigned*)&g_qkvhi[o1] = h1;  *(unsigned*)&g_qkvlo[o1] = l1;
    }
}

// ===========================================================================
// Proj GEMM (fp16 2-term): out = ctx_f16 @ (Whi+Wlo)^T. 128x128 CTA tile,
// 256 threads, 2-stage, 2+ CTAs/SM (61.4 KB smem).
// ===========================================================================
#define OA_MATB 10240u               // 128*80
#define OB_MATB 10240u
#define OSTG (OA_MATB + 2u*OB_MATB)  // 30720
#define GO_SMEM (2u*OSTG)            // 61440

__global__ void __launch_bounds__(256, 2) k_gemm_o(float* __restrict__ Carg)
{
  extern __shared__ __align__(128) char smem[];
  const unsigned sbase = smem_u32(smem);
  const int tid  = threadIdx.x;
  const int lane = tid & 31, wid = tid >> 5;
  const int m0 = blockIdx.y * 128, n0 = blockIdx.x * 128;
  const int K = HID, N = HID;
  const int NC = K / KC;            // 64
  const __half* Af  = (const __half*)g_ahi;
  const __half* Bh  = (const __half*)g_bhi;
  const __half* Bl  = (const __half*)g_blo;

  auto load_chunk = [&](int c) {
    const unsigned st = sbase + (unsigned)(c & 1) * OSTG;
    const int koff = c * KC;
#pragma unroll
    for (int i = 0; i < 6; ++i) {
      const int q = tid + i * 256;     // 1536 16B segs
      unsigned dstoff; const __half* src;
      if (q < 512) {                   // A: 128 rows x 4 segs
        const int row = q >> 2, seg = q & 3;
        dstoff = (unsigned)row * 80u + (unsigned)seg * 16u;
        src = Af + (size_t)(m0 + row) * K + koff + seg * 8;
      } else {                         // B hi/lo: 128 rows x 4 segs each
        const int qq = q - 512, mat = qq >> 9, idx = qq & 511;
        const int row = idx >> 2, seg = idx & 3;
        dstoff = OA_MATB + (unsigned)mat * OB_MATB
               + (unsigned)row * 80u + (unsigned)seg * 16u;
        src = (mat ? Bl : Bh) + (size_t)(n0 + row) * K + koff + seg * 8;
      }
      cp16(st + dstoff, src);
    }
  };

  const int wm = wid & 3, wn = wid >> 2;
  const unsigned aoff0 = (unsigned)(wm*32 + (lane & 15)) * 80u
                       + (unsigned)(lane >> 4) * 16u;
  const unsigned boff0 = OA_MATB
                       + (unsigned)(wn*64 + (lane & 7) + ((lane >> 4) << 3)) * 80u
                       + (unsigned)((lane >> 3) & 1) * 16u;

  float acc[2][8][4];
#pragma unroll
  for (int mi = 0; mi < 2; ++mi)
#pragma unroll
    for (int nt = 0; nt < 8; ++nt)
#pragma unroll
      for (int r = 0; r < 4; ++r) acc[mi][nt][r] = 0.f;

  load_chunk(0); cp_commit();

  for (int c = 0; c < NC; ++c) {
    if (c + 1 < NC) load_chunk(c + 1);
    cp_commit();
    cp_wait1();
    __syncthreads();

    const unsigned st = sbase + (unsigned)(c & 1) * OSTG;
#pragma unroll
    for (int ks = 0; ks < 2; ++ks) {
      unsigned ah[2][4];
#pragma unroll
      for (int mi = 0; mi < 2; ++mi)
        ldsm4(ah[mi], st + aoff0 + (unsigned)mi*1280u + (unsigned)ks*32u);
#pragma unroll
      for (int nj = 0; nj < 4; ++nj) {
        unsigned bh[4], bl[4];
        const unsigned b = st + boff0 + (unsigned)nj*1280u + (unsigned)ks*32u;
        ldsm4(bh, b);
        ldsm4(bl, b + OB_MATB);
#pragma unroll
        for (int mi = 0; mi < 2; ++mi)
#pragma unroll
          for (int hf = 0; hf < 2; ++hf) {
            float* a = acc[mi][nj*2 + hf];
            mma_f16(a, ah[mi], &bh[hf*2]);
            mma_f16(a, ah[mi], &bl[hf*2]);
          }
      }
    }
    __syncthreads();
  }

#pragma unroll
  for (int mi = 0; mi < 2; ++mi)
#pragma unroll
    for (int nt = 0; nt < 8; ++nt) {
      const int r0 = m0 + wm*32 + mi*16 + (lane >> 2);
      const int n  = n0 + wn*64 + nt*8 + (lane & 3)*2;
      *(float2*)&Carg[(size_t)r0 * N + n] =
          make_float2(acc[mi][nt][0], acc[mi][nt][1]);
      *(float2*)&Carg[(size_t)(r0 + 8) * N + n] =
          make_float2(acc[mi][nt][2], acc[mi][nt][3]);
    }
}

// ===========================================================================
// Pipelined HMMA flash attention (causal, bf16 3-term) — unchanged from R14
// except the finalize writes ctx as single fp16 into g_ahi.
// ===========================================================================
#define AT_STR   272u                 // bytes per 128-col bf16 row (+pad)
#define AT_MATB  17408u               // 64*272   (one K or V matrix)
#define AT_KVST  (4u*AT_MATB)         // 69632    (Khi|Klo|Vhi|Vlo)
#define AT_QHI   (2u*AT_KVST)         // 139264
#define AT_QLO   (AT_QHI + 34816u)    // 174080
#define AT_SMEM  (AT_QLO + 34816u)    // 208896

__global__ void __launch_bounds__(256, 1) k_attn()
{
  extern __shared__ __align__(128) char smem[];
  const unsigned sb = smem_u32(smem);
  const int tid = threadIdx.x, lane = tid & 31, w = tid >> 5;
  const int qt = (int)gridDim.x - 1 - (int)blockIdx.x;   // heavy tiles first
  const int h = blockIdx.y, b = blockIdx.z;
  const int q0 = qt * 128;
  const int ktmax = 2*qt + 1;

  const size_t offQ = ((size_t)((0*BATCH + b)*NH + h)) * SEQ * HD;
  const size_t offK = ((size_t)((1*BATCH + b)*NH + h)) * SEQ * HD;
  const size_t offV = ((size_t)((2*BATCH + b)*NH + h)) * SEQ * HD;

  auto stage_k = [&](int kt) {
    const int k0 = kt * 64;
    const unsigned st = sb + (unsigned)(kt & 1) * AT_KVST;
#pragma unroll
    for (int i = 0; i < 8; ++i) {
      const int q = tid + i * 256;            // 2048 segs (K hi+lo)
      const int mat = q >> 10, row = (q >> 4) & 63, seg = q & 15;
      cp16(st + (unsigned)mat * AT_MATB + (unsigned)row * AT_STR + (unsigned)seg * 16u,
           (mat ? g_qkvlo : g_qkvhi) + offK + (size_t)(k0 + row) * HD + seg * 8);
    }
  };
  auto stage_v = [&](int kt) {
    const int k0 = kt * 64;
    const unsigned st = sb + (unsigned)(kt & 1) * AT_KVST + 2u*AT_MATB;
#pragma unroll
    for (int i = 0; i < 8; ++i) {
      const int q = tid + i * 256;            // 2048 segs (V hi+lo)
      const int mat = q >> 10, row = (q >> 4) & 63, seg = q & 15;
      cp16(st + (unsigned)mat * AT_MATB + (unsigned)row * AT_STR + (unsigned)seg * 16u,
           (mat ? g_qkvlo : g_qkvhi) + offV + (size_t)(k0 + row) * HD + seg * 8);
    }
  };

  // Stage Q (hi+lo) into persistent blocks.
#pragma unroll
  for (int i = 0; i < 16; ++i) {
    const int q = tid + i * 256;              // 4096 segs
    const int mat = q >> 11, row = (q >> 4) & 127, seg = q & 15;
    cp16(sb + (mat ? AT_QLO : AT_QHI)
            + (unsigned)row * AT_STR + (unsigned)seg * 16u,
         (mat ? g_qkvlo : g_qkvhi) + offQ + (size_t)(q0 + row) * HD + seg * 8);
  }
  cp_commit();                                // G: Q
  stage_k(0); cp_commit();                    // G: K0
  stage_v(0); cp_commit();                    // G: V0
  stage_k(1); cp_commit();                    // G: K1
  stage_v(1); cp_commit();                    // G: V1

  // ldmatrix per-lane offsets
  const unsigned aoff = (unsigned)(w*16 + (lane & 15)) * AT_STR
                      + (unsigned)(lane >> 4) * 16u;                 // Q rows
  const unsigned boff = (unsigned)((lane & 7) + ((lane >> 4) << 3)) * AT_STR
                      + (unsigned)((lane >> 3) & 1) * 16u;           // K cols
  const unsigned voff = (unsigned)(lane & 15) * AT_STR
                      + (unsigned)(lane >> 4) * 16u;                 // V (trans)

  auto compute_S = [&](unsigned stK, float S[8][4]) {
#pragma unroll
    for (int nb = 0; nb < 8; ++nb)
#pragma unroll
      for (int r = 0; r < 4; ++r) S[nb][r] = 0.f;
#pragma unroll
    for (int kc = 0; kc < 8; ++kc) {
      unsigned qhr[4], qlr[4];
      ldsm4(qhr, sb + AT_QHI + aoff + (unsigned)kc*32u);
      ldsm4(qlr, sb + AT_QLO + aoff + (unsigned)kc*32u);
#pragma unroll
      for (int j = 0; j < 4; ++j) {
        unsigned kh[4], kl[4];
        const unsigned bo = boff + (unsigned)j*4352u + (unsigned)kc*32u;
        ldsm4(kh, stK + bo);
        ldsm4(kl, stK + AT_MATB + bo);
        mma_bf16(S[2*j],   qhr, &kh[0]);  mma_bf16(S[2*j+1], qhr, &kh[2]);
        mma_bf16(S[2*j],   qhr, &kl[0]);  mma_bf16(S[2*j+1], qhr, &kl[2]);
        mma_bf16(S[2*j],   qlr, &kh[0]);  mma_bf16(S[2*j+1], qlr, &kh[2]);
      }
    }
  };

  const float sc = 0.08838834764831845f;   // 1/sqrt(128)
  float m0r = -1e30f, m1r = -1e30f, l0 = 0.f, l1 = 0.f;
  float O[16][4];
#pragma unroll
  for (int nb = 0; nb < 16; ++nb)
#pragma unroll
    for (int r = 0; r < 4; ++r) O[nb][r] = 0.f;

  const int wrow = q0 + w*16;              // warp's first q row

  // Pre-loop: wait {Q, K0}; compute S_0.
  cp_wait3();
  __syncthreads();
  float Scur[8][4];
  compute_S(sb, Scur);

  for (int kt = 0; kt <= ktmax; ++kt) {
    if (kt == ktmax) cp_wait0(); else cp_wait1();
    __syncthreads();

    if (kt + 2 <= ktmax) stage_k(kt + 2);
    cp_commit();

    float Snext[8][4];
    const bool have_next = (kt < ktmax) && ((kt + 1) * 64 <= wrow + 15);
    if (have_next)
      compute_S(sb + (unsigned)((kt + 1) & 1) * AT_KVST, Snext);

    const int k0 = kt * 64;
    const unsigned st = sb + (unsigned)(kt & 1) * AT_KVST;
    if (k0 <= wrow + 15) {
      if (k0 + 63 > wrow) {
        const int rl0 = wrow + (lane >> 2), rl1 = rl0 + 8;
#pragma unroll
        for (int nb = 0; nb < 8; ++nb) {
          const int c0 = k0 + nb*8 + 2*(lane & 3), c1 = c0 + 1;
          if (c0 > rl0) Scur[nb][0] = -1e30f;
          if (c1 > rl0) Scur[nb][1] = -1e30f;
          if (c0 > rl1) Scur[nb][2] = -1e30f;
          if (c1 > rl1) Scur[nb][3] = -1e30f;
        }
      }

      float mx0 = -1e30f, mx1 = -1e30f;
#pragma unroll
      for (int nb = 0; nb < 8; ++nb) {
        mx0 = fmaxf(mx0, fmaxf(Scur[nb][0], Scur[nb][1]));
        mx1 = fmaxf(mx1, fmaxf(Scur[nb][2], Scur[nb][3]));
      }
      mx0 = fmaxf(mx0, __shfl_xor_sync(0xFFFFFFFFu, mx0, 1));
      mx0 = fmaxf(mx0, __shfl_xor_sync(0xFFFFFFFFu, mx0, 2));
      mx1 = fmaxf(mx1, __shfl_xor_sync(0xFFFFFFFFu, mx1, 1));
      mx1 = fmaxf(mx1, __shfl_xor_sync(0xFFFFFFFFu, mx1, 2));
      const float mn0 = fmaxf(m0r, mx0), mn1 = fmaxf(m1r, mx1);
      const float a0 = __expf(sc * (m0r - mn0));
      const float a1 = __expf(sc * (m1r - mn1));
      m0r = mn0; m1r = mn1;

      float ls0 = 0.f, ls1 = 0.f;
#pragma unroll
      for (int nb = 0; nb < 8; ++nb) {
        Scur[nb][0] = __expf(sc * (Scur[nb][0] - mn0));
        Scur[nb][1] = __expf(sc * (Scur[nb][1] - mn0));
        Scur[nb][2] = __expf(sc * (Scur[nb][2] - mn1));
        Scur[nb][3] = __expf(sc * (Scur[nb][3] - mn1));
        ls0 += Scur[nb][0] + Scur[nb][1];
        ls1 += Scur[nb][2] + Scur[nb][3];
      }
      l0 = l0 * a0 + ls0;
      l1 = l1 * a1 + ls1;

#pragma unroll
      for (int nb = 0; nb < 16; ++nb) {
        O[nb][0] *= a0; O[nb][1] *= a0;
        O[nb][2] *= a1; O[nb][3] *= a1;
      }

      unsigned ph[4][4], pl[4][4];
#pragma unroll
      for (int kc2 = 0; kc2 < 4; ++kc2) {
        const float* p0 = Scur[2*kc2];
        const float* p1 = Scur[2*kc2+1];
        ph[kc2][0] = packbf(p0[0], p0[1]);
        ph[kc2][1] = packbf(p0[2], p0[3]);
        ph[kc2][2] = packbf(p1[0], p1[1]);
        ph[kc2][3] = packbf(p1[2], p1[3]);
        pl[kc2][0] = packbf(p0[0] - blo(ph[kc2][0]), p0[1] - bhif(ph[kc2][0]));
        pl[kc2][1] = packbf(p0[2] - blo(ph[kc2][1]), p0[3] - bhif(ph[kc2][1]));
        pl[kc2][2] = packbf(p1[0] - blo(ph[kc2][2]), p1[1] - bhif(ph[kc2][2]));
        pl[kc2][3] = packbf(p1[2] - blo(ph[kc2][3]), p1[3] - bhif(ph[kc2][3]));
      }

#pragma unroll
      for (int kc2 = 0; kc2 < 4; ++kc2) {
#pragma unroll
        for (int j = 0; j < 8; ++j) {
          unsigned vh[4], vl[4];
          const unsigned vo = voff + (unsigned)kc2*4352u + (unsigned)j*32u;
          ldsm4t(vh, st + 2*AT_MATB + vo);
          ldsm4t(vl, st + 3*AT_MATB + vo);
          mma_bf16(O[2*j],   ph[kc2], &vh[0]);  mma_bf16(O[2*j+1], ph[kc2], &vh[2]);
          mma_bf16(O[2*j],   ph[kc2], &vl[0]);  mma_bf16(O[2*j+1], ph[kc2], &vl[2]);
          mma_bf16(O[2*j],   pl[kc2], &vh[0]);  mma_bf16(O[2*j+1], pl[kc2], &vh[2]);
        }
      }
    }

    __syncthreads();
    if (kt + 2 <= ktmax) stage_v(kt + 2);
    cp_commit();

    if (have_next) {
#pragma unroll
      for (int nb = 0; nb < 8; ++nb)
#pragma unroll
        for (int r = 0; r < 4; ++r) Scur[nb][r] = Snext[nb][r];
    }
  }

  // ---- finalize: normalize, write ctx as single fp16 into g_ahi ----
  l0 += __shfl_xor_sync(0xFFFFFFFFu, l0, 1);
  l0 += __shfl_xor_sync(0xFFFFFFFFu, l0, 2);
  l1 += __shfl_xor_sync(0xFFFFFFFFu, l1, 1);
  l1 += __shfl_xor_sync(0xFFFFFFFFu, l1, 2);
  const float inv0 = 1.f / l0, inv1 = 1.f / l1;

  __half* ctx = (__half*)g_ahi;
  const int s0 = q0 + w*16 + (lane >> 2), s1 = s0 + 8;
  const size_t rb0 = ((size_t)b*SEQ + s0) * HID + h*HD;
  const size_t rb1 = ((size_t)b*SEQ + s1) * HID + h*HD;
#pragma unroll
  for (int nb = 0; nb < 16; ++nb) {
    const int c = nb*8 + 2*(lane & 3);
    const unsigned f0 = packf16(O[nb][0]*inv0, O[nb][1]*inv0);
    const unsigned f1 = packf16(O[nb][2]*inv1, O[nb][3]*inv1);
    *(unsigned*)&ctx[rb0 + c] = f0;
    *(unsigned*)&ctx[rb1 + c] = f1;
  }
}

// ---------------------------------------------------------------------------
extern "C" void kernel_launch(void* const* d_in, const int* in_sizes, int n_in,
                              void* d_out, int out_size)
{
  const float* x     = (const float*)d_in[0];
  const float* w_qkv = (const float*)d_in[1];
  const float* b_qkv = (const float*)d_in[2];
  const float* w_o   = (const float*)d_in[3];
  float* out = (float*)d_out;

  cudaFuncSetAttribute(k_gemm_qkv, cudaFuncAttributeMaxDynamicSharedMemorySize, GQ_SMEM);
  cudaFuncSetAttribute(k_gemm_o,   cudaFuncAttributeMaxDynamicSharedMemorySize, GO_SMEM);
  cudaFuncSetAttribute(k_attn,     cudaFuncAttributeMaxDynamicSharedMemorySize, AT_SMEM);

  const int n4x = MTOT*HID/4;   // 2,097,152

  // 1) convert x -> fp16; transpose+split w_qkv -> fp16 hi/lo
  k_split<<<(n4x + 255)/256, 256>>>((const float4*)x, n4x);
  k_splitT<<<dim3(QKVN/32, HID/32), 256>>>(w_qkv, QKVN);
  // 2) QKV GEMM (fp16 2-term) -> head-major bf16 hi/lo q/k/v (+bias fused)
  k_gemm_qkv<<<dim3(QKVN/128, MTOT/64), 128, GQ_SMEM>>>(b_qkv);
  // 3) HMMA flash attention (bf16 3-term) -> ctx fp16 into g_ahi
  k_attn<<<dim3(SEQ/128, NH, BATCH), 256, AT_SMEM>>>();
  // 4) transpose+split w_o -> fp16 hi/lo
  k_splitT<<<dim3(HID/32, HID/32), 256>>>(w_o, HID);
  // 5) output projection (fp16 2-term) -> d_out
  k_gemm_o<<<dim3(HID/128, MTOT/128), 256, GO_SMEM>>>(out);
}

// round 16
// speedup vs baseline: 1.3575x; 1.0918x over previous
#include <cuda_runtime.h>
#include <cuda_bf16.h>
#include <cuda_fp16.h>
#include <cstdint>
#include <cstddef>

// Problem constants (fixed shapes).
#define BATCH 2
#define SEQ   2048
#define HID   2048
#define NH    16
#define HD    128
#define QKVN  (3*HID)   // 6144
#define MTOT  (BATCH*SEQ)

// Scratch (device globals; no allocations allowed). fp16 payloads in bf16-typed
// buffers (byte-compatible).
__device__ __nv_bfloat16 g_ahi[(size_t)MTOT*HID];        // fp16 A (x, later ctx)
__device__ __nv_bfloat16 g_alo[(size_t)MTOT*HID];        // (unused)
__device__ __nv_bfloat16 g_bhi[(size_t)QKVN*HID];        // fp16 weights^T hi [N][2048]
__device__ __nv_bfloat16 g_blo[(size_t)QKVN*HID];        // fp16 weights^T lo
__device__ __nv_bfloat16 g_qkvhi[(size_t)3*BATCH*NH*SEQ*HD];  // fp16: Qhi | K | V
__device__ __nv_bfloat16 g_qkvlo[(size_t)3*BATCH*NH*SEQ*HD];  // fp16: Qlo (which=0 only)

// ===========================================================================
// PTX helpers
// ===========================================================================
__device__ __forceinline__ unsigned smem_u32(const void* p) {
  unsigned a;
  asm("{ .reg .u64 t; cvta.to.shared.u64 t, %1; cvt.u32.u64 %0, t; }"
      : "=r"(a) : "l"(p));
  return a;
}
__device__ __forceinline__ void cp16(unsigned dst, const void* src) {
  asm volatile("cp.async.cg.shared.global [%0], [%1], 16;"
               :: "r"(dst), "l"(__cvta_generic_to_global(src)));
}
__device__ __forceinline__ void cp_commit() {
  asm volatile("cp.async.commit_group;" ::: "memory");
}
__device__ __forceinline__ void cp_wait0() {
  asm volatile("cp.async.wait_group 0;" ::: "memory");
}
__device__ __forceinline__ void cp_wait1() {
  asm volatile("cp.async.wait_group 1;" ::: "memory");
}
__device__ __forceinline__ void cp_wait3() {
  asm volatile("cp.async.wait_group 3;" ::: "memory");
}
__device__ __forceinline__ void ldsm4(unsigned* r, unsigned addr) {
  asm volatile("ldmatrix.sync.aligned.m8n8.x4.shared.b16 {%0,%1,%2,%3}, [%4];"
               : "=r"(r[0]), "=r"(r[1]), "=r"(r[2]), "=r"(r[3]) : "r"(addr));
}
__device__ __forceinline__ void ldsm4t(unsigned* r, unsigned addr) {
  asm volatile("ldmatrix.sync.aligned.m8n8.x4.trans.shared.b16 {%0,%1,%2,%3}, [%4];"
               : "=r"(r[0]), "=r"(r[1]), "=r"(r[2]), "=r"(r[3]) : "r"(addr));
}
__device__ __forceinline__ void mma_f16(float* d, const unsigned* a,
                                        const unsigned* b) {
  asm volatile(
    "mma.sync.aligned.m16n8k16.row.col.f32.f16.f16.f32 "
    "{%0,%1,%2,%3}, {%4,%5,%6,%7}, {%8,%9}, {%0,%1,%2,%3};"
    : "+f"(d[0]), "+f"(d[1]), "+f"(d[2]), "+f"(d[3])
    : "r"(a[0]), "r"(a[1]), "r"(a[2]), "r"(a[3]), "r"(b[0]), "r"(b[1]));
}
__device__ __forceinline__ unsigned packf16(float lo, float hi) {
  unsigned r;
  asm("cvt.rn.f16x2.f32 %0, %1, %2;" : "=r"(r) : "f"(hi), "f"(lo));
  return r;
}
__device__ __forceinline__ float f16lo(unsigned r) {
  __half2 h = *(__half2*)&r; return __low2float(h);
}
__device__ __forceinline__ float f16hi(unsigned r) {
  __half2 h = *(__half2*)&r; return __high2float(h);
}

// ===========================================================================
// fp32 -> fp16 convert (elementwise) into g_ahi (as __half)
// ===========================================================================
__global__ void __launch_bounds__(256) k_split(const float4* __restrict__ in,
                                               int n4)
{
  int i = blockIdx.x * 256 + threadIdx.x;
  if (i >= n4) return;
  float4 v = in[i];
  __half2* o = (__half2*)g_ahi;
  o[2*i]   = __floats2half2_rn(v.x, v.y);
  o[2*i+1] = __floats2half2_rn(v.z, v.w);
}

// ===========================================================================
// w [K=2048][N] fp32 -> transposed fp16 hi/lo [N][2048] into g_bhi/g_blo
// ===========================================================================
__global__ void __launch_bounds__(256) k_splitT(const float* __restrict__ w,
                                                int N)
{
  __shared__ float t[32][33];
  const int n0 = blockIdx.x * 32, k0 = blockIdx.y * 32;
  const int tx = threadIdx.x & 31, ty = threadIdx.x >> 5;
#pragma unroll
  for (int i = 0; i < 4; ++i)
    t[ty + i*8][tx] = w[(size_t)(k0 + ty + i*8) * N + n0 + tx];
  __syncthreads();
#pragma unroll
  for (int i = 0; i < 4; ++i) {
    const int n = n0 + ty + i*8, k = k0 + tx;
    float v = t[tx][ty + i*8];
    __half h = __float2half_rn(v);
    ((__half*)g_bhi)[(size_t)n * HID + k] = h;
    ((__half*)g_blo)[(size_t)n * HID + k] = __float2half_rn(v - __half2float(h));
  }
}

// ===========================================================================
// QKV GEMM (fp16 2-term): 64x128 CTA tile, 128 threads, KC=32, 3 CTAs/SM.
// Epilogue: Q -> fp16 hi/lo (g_qkvhi/g_qkvlo), K/V -> single fp16 (g_qkvhi).
// ===========================================================================
#define KC 32
#define QA_MATB 5120u                // 64*80
#define QB_MATB 10240u               // 128*80
#define QSTG (QA_MATB + 2u*QB_MATB)  // 25600
#define GQ_SMEM (2u*QSTG)            // 51200

__global__ void __launch_bounds__(128, 3) k_gemm_qkv(const float* __restrict__ bias)
{
  extern __shared__ __align__(128) char smem[];
  const unsigned sbase = smem_u32(smem);
  const int tid  = threadIdx.x;
  const int lane = tid & 31, wid = tid >> 5;
  const int m0 = blockIdx.y * 64, n0 = blockIdx.x * 128;
  const int K = HID;
  const int NC = K / KC;            // 64
  const __half* Af  = (const __half*)g_ahi;
  const __half* Bh  = (const __half*)g_bhi;
  const __half* Bl  = (const __half*)g_blo;

  auto load_chunk = [&](int c) {
    const unsigned st = sbase + (unsigned)(c & 1) * QSTG;
    const int koff = c * KC;
#pragma unroll
    for (int i = 0; i < 10; ++i) {
      const int q = tid + i * 128;     // 1280 16B segs
      unsigned dstoff; const __half* src;
      if (q < 256) {                   // A: 64 rows x 4 segs
        const int row = q >> 2, seg = q & 3;
        dstoff = (unsigned)row * 80u + (unsigned)seg * 16u;
        src = Af + (size_t)(m0 + row) * K + koff + seg * 8;
      } else {                         // B hi/lo: 128 rows x 4 segs each
        const int qq = q - 256, mat = qq >> 9, idx = qq & 511;
        const int row = idx >> 2, seg = idx & 3;
        dstoff = QA_MATB + (unsigned)mat * QB_MATB
               + (unsigned)row * 80u + (unsigned)seg * 16u;
        src = (mat ? Bl : Bh) + (size_t)(n0 + row) * K + koff + seg * 8;
      }
      cp16(st + dstoff, src);
    }
  };

  const int wm = wid & 1, wn = wid >> 1;
  const unsigned aoff0 = (unsigned)(wm*32 + (lane & 15)) * 80u
                       + (unsigned)(lane >> 4) * 16u;
  const unsigned boff0 = QA_MATB
                       + (unsigned)(wn*64 + (lane & 7) + ((lane >> 4) << 3)) * 80u
                       + (unsigned)((lane >> 3) & 1) * 16u;

  float acc[2][8][4];
#pragma unroll
  for (int mi = 0; mi < 2; ++mi)
#pragma unroll
    for (int nt = 0; nt < 8; ++nt)
#pragma unroll
      for (int r = 0; r < 4; ++r) acc[mi][nt][r] = 0.f;

  load_chunk(0); cp_commit();

  for (int c = 0; c < NC; ++c) {
    if (c + 1 < NC) load_chunk(c + 1);
    cp_commit();
    cp_wait1();
    __syncthreads();

    const unsigned st = sbase + (unsigned)(c & 1) * QSTG;
#pragma unroll
    for (int ks = 0; ks < 2; ++ks) {
      unsigned ah[2][4];
#pragma unroll
      for (int mi = 0; mi < 2; ++mi)
        ldsm4(ah[mi], st + aoff0 + (unsigned)mi*1280u + (unsigned)ks*32u);
#pragma unroll
      for (int nj = 0; nj < 4; ++nj) {
        unsigned bh[4], bl[4];
        const unsigned b = st + boff0 + (unsigned)nj*1280u + (unsigned)ks*32u;
        ldsm4(bh, b);
        ldsm4(bl, b + QB_MATB);
#pragma unroll
        for (int mi = 0; mi < 2; ++mi)
#pragma unroll
          for (int hf = 0; hf < 2; ++hf) {
            float* a = acc[mi][nj*2 + hf];
            mma_f16(a, ah[mi], &bh[hf*2]);
            mma_f16(a, ah[mi], &bl[hf*2]);
          }
      }
    }
    __syncthreads();
  }

  // Epilogue: bias + store head-major q/k/v (Q fp16 hi/lo; K,V single fp16).
  __half* qkvh = (__half*)g_qkvhi;
  __half* qkvl = (__half*)g_qkvlo;
#pragma unroll
  for (int mi = 0; mi < 2; ++mi)
#pragma unroll
    for (int nt = 0; nt < 8; ++nt) {
      const int r0 = m0 + wm*32 + mi*16 + (lane >> 2);
      const int n  = n0 + wn*64 + nt*8 + (lane & 3)*2;
      const float2 bv = *(const float2*)&bias[n];
      const float p0 = acc[mi][nt][0] + bv.x, p1 = acc[mi][nt][1] + bv.y;
      const float p2 = acc[mi][nt][2] + bv.x, p3 = acc[mi][nt][3] + bv.y;
      const int which = n >> 11, hh = (n >> 7) & 15, dd = n & 127;
      const int bb = r0 >> 11, s = r0 & 2047;
      const size_t o0 = ((size_t)((which*BATCH + bb)*NH + hh) * SEQ + s) * HD + dd;
      const size_t o1 = o0 + 8*HD;
      const unsigned h0 = packf16(p0, p1);
      const unsigned h1 = packf16(p2, p3);
      *(unsigned*)&qkvh[o0] = h0;
      *(unsigned*)&qkvh[o1] = h1;
      if (which == 0) {
        const unsigned l0 = packf16(p0 - f16lo(h0), p1 - f16hi(h0));
        const unsigned l1 = packf16(p2 - f16lo(h1), p3 - f16hi(h1));
        *(unsigned*)&qkvl[o0] = l0;
        *(unsigned*)&qkvl[o1] = l1;
      }
    }
}

// ===========================================================================
// Proj GEMM (fp16 2-term): 128x128 CTA tile, 256 threads, 2 CTAs/SM.
// ===========================================================================
#define OA_MATB 10240u               // 128*80
#define OB_MATB 10240u
#define OSTG (OA_MATB + 2u*OB_MATB)  // 30720
#define GO_SMEM (2u*OSTG)            // 61440

__global__ void __launch_bounds__(256, 2) k_gemm_o(float* __restrict__ Carg)
{
  extern __shared__ __align__(128) char smem[];
  const unsigned sbase = smem_u32(smem);
  const int tid  = threadIdx.x;
  const int lane = tid & 31, wid = tid >> 5;
  const int m0 = blockIdx.y * 128, n0 = blockIdx.x * 128;
  const int K = HID, N = HID;
  const int NC = K / KC;            // 64
  const __half* Af  = (const __half*)g_ahi;
  const __half* Bh  = (const __half*)g_bhi;
  const __half* Bl  = (const __half*)g_blo;

  auto load_chunk = [&](int c) {
    const unsigned st = sbase + (unsigned)(c & 1) * OSTG;
    const int koff = c * KC;
#pragma unroll
    for (int i = 0; i < 6; ++i) {
      const int q = tid + i * 256;     // 1536 16B segs
      unsigned dstoff; const __half* src;
      if (q < 512) {                   // A: 128 rows x 4 segs
        const int row = q >> 2, seg = q & 3;
        dstoff = (unsigned)row * 80u + (unsigned)seg * 16u;
        src = Af + (size_t)(m0 + row) * K + koff + seg * 8;
      } else {                         // B hi/lo: 128 rows x 4 segs each
        const int qq = q - 512, mat = qq >> 9, idx = qq & 511;
        const int row = idx >> 2, seg = idx & 3;
        dstoff = OA_MATB + (unsigned)mat * OB_MATB
               + (unsigned)row * 80u + (unsigned)seg * 16u;
        src = (mat ? Bl : Bh) + (size_t)(n0 + row) * K + koff + seg * 8;
      }
      cp16(st + dstoff, src);
    }
  };

  const int wm = wid & 3, wn = wid >> 2;
  const unsigned aoff0 = (unsigned)(wm*32 + (lane & 15)) * 80u
                       + (unsigned)(lane >> 4) * 16u;
  const unsigned boff0 = OA_MATB
                       + (unsigned)(wn*64 + (lane & 7) + ((lane >> 4) << 3)) * 80u
                       + (unsigned)((lane >> 3) & 1) * 16u;

  float acc[2][8][4];
#pragma unroll
  for (int mi = 0; mi < 2; ++mi)
#pragma unroll
    for (int nt = 0; nt < 8; ++nt)
#pragma unroll
      for (int r = 0; r < 4; ++r) acc[mi][nt][r] = 0.f;

  load_chunk(0); cp_commit();

  for (int c = 0; c < NC; ++c) {
    if (c + 1 < NC) load_chunk(c + 1);
    cp_commit();
    cp_wait1();
    __syncthreads();

    const unsigned st = sbase + (unsigned)(c & 1) * OSTG;
#pragma unroll
    for (int ks = 0; ks < 2; ++ks) {
      unsigned ah[2][4];
#pragma unroll
      for (int mi = 0; mi < 2; ++mi)
        ldsm4(ah[mi], st + aoff0 + (unsigned)mi*1280u + (unsigned)ks*32u);
#pragma unroll
      for (int nj = 0; nj < 4; ++nj) {
        unsigned bh[4], bl[4];
        const unsigned b = st + boff0 + (unsigned)nj*1280u + (unsigned)ks*32u;
        ldsm4(bh, b);
        ldsm4(bl, b + OB_MATB);
#pragma unroll
        for (int mi = 0; mi < 2; ++mi)
#pragma unroll
          for (int hf = 0; hf < 2; ++hf) {
            float* a = acc[mi][nj*2 + hf];
            mma_f16(a, ah[mi], &bh[hf*2]);
            mma_f16(a, ah[mi], &bl[hf*2]);
          }
      }
    }
    __syncthreads();
  }

#pragma unroll
  for (int mi = 0; mi < 2; ++mi)
#pragma unroll
    for (int nt = 0; nt < 8; ++nt) {
      const int r0 = m0 + wm*32 + mi*16 + (lane >> 2);
      const int n  = n0 + wn*64 + nt*8 + (lane & 3)*2;
      *(float2*)&Carg[(size_t)r0 * N + n] =
          make_float2(acc[mi][nt][0], acc[mi][nt][1]);
      *(float2*)&Carg[(size_t)(r0 + 8) * N + n] =
          make_float2(acc[mi][nt][2], acc[mi][nt][3]);
    }
}

// ===========================================================================
// Pipelined fp16 flash attention (causal). 256 threads, q-tile 128, k-tile 64.
// S = (Qhi+Qlo) * K (K single fp16, 2 MMA terms); PV = (Phi+Plo) * V (V single
// fp16). K/V staging halved vs bf16 3-term. Structure as R14 (S_next issued
// before softmax of S_cur; K and V staged separately; wait_group(1) ledger).
// ===========================================================================
#define AT_STR   272u                 // bytes per 128-col fp16 row (+pad)
#define AT_MATB  17408u               // 64*272  (one K or V matrix)
#define AT_KVST  (2u*AT_MATB)         // 34816   (K | V)
#define AT_QHI   (2u*AT_KVST)         // 69632
#define AT_QLO   (AT_QHI + 34816u)    // 104448
#define AT_SMEM  (AT_QLO + 34816u)    // 139264

__global__ void __launch_bounds__(256, 1) k_attn()
{
  extern __shared__ __align__(128) char smem[];
  const unsigned sb = smem_u32(smem);
  const int tid = threadIdx.x, lane = tid & 31, w = tid >> 5;
  const int qt = (int)gridDim.x - 1 - (int)blockIdx.x;   // heavy tiles first
  const int h = blockIdx.y, b = blockIdx.z;
  const int q0 = qt * 128;
  const int ktmax = 2*qt + 1;

  const __half* qkvh = (const __half*)g_qkvhi;
  const __half* qkvl = (const __half*)g_qkvlo;
  const size_t offQ = ((size_t)((0*BATCH + b)*NH + h)) * SEQ * HD;
  const size_t offK = ((size_t)((1*BATCH + b)*NH + h)) * SEQ * HD;
  const size_t offV = ((size_t)((2*BATCH + b)*NH + h)) * SEQ * HD;

  auto stage_k = [&](int kt) {
    const int k0 = kt * 64;
    const unsigned st = sb + (unsigned)(kt & 1) * AT_KVST;
#pragma unroll
    for (int i = 0; i < 4; ++i) {
      const int q = tid + i * 256;            // 1024 segs
      const int row = q >> 4, seg = q & 15;
      cp16(st + (unsigned)row * AT_STR + (unsigned)seg * 16u,
           qkvh + offK + (size_t)(k0 + row) * HD + seg * 8);
    }
  };
  auto stage_v = [&](int kt) {
    const int k0 = kt * 64;
    const unsigned st = sb + (unsigned)(kt & 1) * AT_KVST + AT_MATB;
#pragma unroll
    for (int i = 0; i < 4; ++i) {
      const int q = tid + i * 256;            // 1024 segs
      const int row = q >> 4, seg = q & 15;
      cp16(st + (unsigned)row * AT_STR + (unsigned)seg * 16u,
           qkvh + offV + (size_t)(k0 + row) * HD + seg * 8);
    }
  };

  // Stage Q (hi+lo) into persistent blocks.
#pragma unroll
  for (int i = 0; i < 16; ++i) {
    const int q = tid + i * 256;              // 4096 segs
    const int mat = q >> 11, row = (q >> 4) & 127, seg = q & 15;
    cp16(sb + (mat ? AT_QLO : AT_QHI)
            + (unsigned)row * AT_STR + (unsigned)seg * 16u,
         (mat ? qkvl : qkvh) + offQ + (size_t)(q0 + row) * HD + seg * 8);
  }
  cp_commit();                                // G: Q
  stage_k(0); cp_commit();                    // G: K0
  stage_v(0); cp_commit();                    // G: V0
  stage_k(1); cp_commit();                    // G: K1
  stage_v(1); cp_commit();                    // G: V1

  // ldmatrix per-lane offsets
  const unsigned aoff = (unsigned)(w*16 + (lane & 15)) * AT_STR
                      + (unsigned)(lane >> 4) * 16u;                 // Q rows
  const unsigned boff = (unsigned)((lane & 7) + ((lane >> 4) << 3)) * AT_STR
                      + (unsigned)((lane >> 3) & 1) * 16u;           // K cols
  const unsigned voff = (unsigned)(lane & 15) * AT_STR
                      + (unsigned)(lane >> 4) * 16u;                 // V (trans)

  // S = (Qhi+Qlo) K^T (2-term fp16) for the K tile at slot base stK.
  auto compute_S = [&](unsigned stK, float S[8][4]) {
#pragma unroll
    for (int nb = 0; nb < 8; ++nb)
#pragma unroll
      for (int r = 0; r < 4; ++r) S[nb][r] = 0.f;
#pragma unroll
    for (int kc = 0; kc < 8; ++kc) {
      unsigned qhr[4], qlr[4];
      ldsm4(qhr, sb + AT_QHI + aoff + (unsigned)kc*32u);
      ldsm4(qlr, sb + AT_QLO + aoff + (unsigned)kc*32u);
#pragma unroll
      for (int j = 0; j < 4; ++j) {
        unsigned kf[4];
        ldsm4(kf, stK + boff + (unsigned)j*4352u + (unsigned)kc*32u);
        mma_f16(S[2*j],   qhr, &kf[0]);  mma_f16(S[2*j+1], qhr, &kf[2]);
        mma_f16(S[2*j],   qlr, &kf[0]);  mma_f16(S[2*j+1], qlr, &kf[2]);
      }
    }
  };

  const float sc = 0.08838834764831845f;   // 1/sqrt(128)
  float m0r = -1e30f, m1r = -1e30f, l0 = 0.f, l1 = 0.f;
  float O[16][4];
#pragma unroll
  for (int nb = 0; nb < 16; ++nb)
#pragma unroll
    for (int r = 0; r < 4; ++r) O[nb][r] = 0.f;

  const int wrow = q0 + w*16;              // warp's first q row

  // Pre-loop: wait {Q, K0}; compute S_0.
  cp_wait3();
  __syncthreads();
  float Scur[8][4];
  compute_S(sb, Scur);

  for (int kt = 0; kt <= ktmax; ++kt) {
    if (kt == ktmax) cp_wait0(); else cp_wait1();
    __syncthreads();

    if (kt + 2 <= ktmax) stage_k(kt + 2);
    cp_commit();

    float Snext[8][4];
    const bool have_next = (kt < ktmax) && ((kt + 1) * 64 <= wrow + 15);
    if (have_next)
      compute_S(sb + (unsigned)((kt + 1) & 1) * AT_KVST, Snext);

    const int k0 = kt * 64;
    const unsigned st = sb + (unsigned)(kt & 1) * AT_KVST;
    if (k0 <= wrow + 15) {
      if (k0 + 63 > wrow) {
        const int rl0 = wrow + (lane >> 2), rl1 = rl0 + 8;
#pragma unroll
        for (int nb = 0; nb < 8; ++nb) {
          const int c0 = k0 + nb*8 + 2*(lane & 3), c1 = c0 + 1;
          if (c0 > rl0) Scur[nb][0] = -1e30f;
          if (c1 > rl0) Scur[nb][1] = -1e30f;
          if (c0 > rl1) Scur[nb][2] = -1e30f;
          if (c1 > rl1) Scur[nb][3] = -1e30f;
        }
      }

      float mx0 = -1e30f, mx1 = -1e30f;
#pragma unroll
      for (int nb = 0; nb < 8; ++nb) {
        mx0 = fmaxf(mx0, fmaxf(Scur[nb][0], Scur[nb][1]));
        mx1 = fmaxf(mx1, fmaxf(Scur[nb][2], Scur[nb][3]));
      }
      mx0 = fmaxf(mx0, __shfl_xor_sync(0xFFFFFFFFu, mx0, 1));
      mx0 = fmaxf(mx0, __shfl_xor_sync(0xFFFFFFFFu, mx0, 2));
      mx1 = fmaxf(mx1, __shfl_xor_sync(0xFFFFFFFFu, mx1, 1));
      mx1 = fmaxf(mx1, __shfl_xor_sync(0xFFFFFFFFu, mx1, 2));
      const float mn0 = fmaxf(m0r, mx0), mn1 = fmaxf(m1r, mx1);
      const float a0 = __expf(sc * (m0r - mn0));
      const float a1 = __expf(sc * (m1r - mn1));
      m0r = mn0; m1r = mn1;

      float ls0 = 0.f, ls1 = 0.f;
#pragma unroll
      for (int nb = 0; nb < 8; ++nb) {
        Scur[nb][0] = __expf(sc * (Scur[nb][0] - mn0));
        Scur[nb][1] = __expf(sc * (Scur[nb][1] - mn0));
        Scur[nb][2] = __expf(sc * (Scur[nb][2] - mn1));
        Scur[nb][3] = __expf(sc * (Scur[nb][3] - mn1));
        ls0 += Scur[nb][0] + Scur[nb][1];
        ls1 += Scur[nb][2] + Scur[nb][3];
      }
      l0 = l0 * a0 + ls0;
      l1 = l1 * a1 + ls1;

#pragma unroll
      for (int nb = 0; nb < 16; ++nb) {
        O[nb][0] *= a0; O[nb][1] *= a0;
        O[nb][2] *= a1; O[nb][3] *= a1;
      }

      // ---- P hi/lo fp16 fragments ----
      unsigned ph[4][4], pl[4][4];
#pragma unroll
      for (int kc2 = 0; kc2 < 4; ++kc2) {
        const float* p0 = Scur[2*kc2];
        const float* p1 = Scur[2*kc2+1];
        ph[kc2][0] = packf16(p0[0], p0[1]);
        ph[kc2][1] = packf16(p0[2], p0[3]);
        ph[kc2][2] = packf16(p1[0], p1[1]);
        ph[kc2][3] = packf16(p1[2], p1[3]);
        pl[kc2][0] = packf16(p0[0] - f16lo(ph[kc2][0]), p0[1] - f16hi(ph[kc2][0]));
        pl[kc2][1] = packf16(p0[2] - f16lo(ph[kc2][1]), p0[3] - f16hi(ph[kc2][1]));
        pl[kc2][2] = packf16(p1[0] - f16lo(ph[kc2][2]), p1[1] - f16hi(ph[kc2][2]));
        pl[kc2][3] = packf16(p1[2] - f16lo(ph[kc2][3]), p1[3] - f16hi(ph[kc2][3]));
      }

      // ---- O += (Phi+Plo) V (V single fp16), 16x128 ----
#pragma unroll
      for (int kc2 = 0; kc2 < 4; ++kc2) {
#pragma unroll
        for (int j = 0; j < 8; ++j) {
          unsigned vf[4];
          ldsm4t(vf, st + AT_MATB + voff + (unsigned)kc2*4352u + (unsigned)j*32u);
          mma_f16(O[2*j],   ph[kc2], &vf[0]);  mma_f16(O[2*j+1], ph[kc2], &vf[2]);
          mma_f16(O[2*j],   pl[kc2], &vf[0]);  mma_f16(O[2*j+1], pl[kc2], &vf[2]);
        }
      }
    }

    __syncthreads();       // all warps done with V(kt) before restage
    if (kt + 2 <= ktmax) stage_v(kt + 2);
    cp_commit();

    if (have_next) {
#pragma unroll
      for (int nb = 0; nb < 8; ++nb)
#pragma unroll
        for (int r = 0; r < 4; ++r) Scur[nb][r] = Snext[nb][r];
    }
  }

  // ---- finalize: normalize, write ctx as single fp16 into g_ahi ----
  l0 += __shfl_xor_sync(0xFFFFFFFFu, l0, 1);
  l0 += __shfl_xor_sync(0xFFFFFFFFu, l0, 2);
  l1 += __shfl_xor_sync(0xFFFFFFFFu, l1, 1);
  l1 += __shfl_xor_sync(0xFFFFFFFFu, l1, 2);
  const float inv0 = 1.f / l0, inv1 = 1.f / l1;

  __half* ctx = (__half*)g_ahi;
  const int s0 = q0 + w*16 + (lane >> 2), s1 = s0 + 8;
  const size_t rb0 = ((size_t)b*SEQ + s0) * HID + h*HD;
  const size_t rb1 = ((size_t)b*SEQ + s1) * HID + h*HD;
#pragma unroll
  for (int nb = 0; nb < 16; ++nb) {
    const int c = nb*8 + 2*(lane & 3);
    const unsigned f0 = packf16(O[nb][0]*inv0, O[nb][1]*inv0);
    const unsigned f1 = packf16(O[nb][2]*inv1, O[nb][3]*inv1);
    *(unsigned*)&ctx[rb0 + c] = f0;
    *(unsigned*)&ctx[rb1 + c] = f1;
  }
}

// ---------------------------------------------------------------------------
extern "C" void kernel_launch(void* const* d_in, const int* in_sizes, int n_in,
                              void* d_out, int out_size)
{
  const float* x     = (const float*)d_in[0];
  const float* w_qkv = (const float*)d_in[1];
  const float* b_qkv = (const float*)d_in[2];
  const float* w_o   = (const float*)d_in[3];
  float* out = (float*)d_out;

  cudaFuncSetAttribute(k_gemm_qkv, cudaFuncAttributeMaxDynamicSharedMemorySize, GQ_SMEM);
  cudaFuncSetAttribute(k_gemm_o,   cudaFuncAttributeMaxDynamicSharedMemorySize, GO_SMEM);
  cudaFuncSetAttribute(k_attn,     cudaFuncAttributeMaxDynamicSharedMemorySize, AT_SMEM);

  const int n4x = MTOT*HID/4;   // 2,097,152

  // 1) convert x -> fp16; transpose+split w_qkv -> fp16 hi/lo
  k_split<<<(n4x + 255)/256, 256>>>((const float4*)x, n4x);
  k_splitT<<<dim3(QKVN/32, HID/32), 256>>>(w_qkv, QKVN);
  // 2) QKV GEMM (fp16 2-term) -> head-major fp16 (Q hi/lo, K/V single)
  k_gemm_qkv<<<dim3(QKVN/128, MTOT/64), 128, GQ_SMEM>>>(b_qkv);
  // 3) fp16 flash attention (2-term S, 2-term PV) -> ctx fp16 into g_ahi
  k_attn<<<dim3(SEQ/128, NH, BATCH), 256, AT_SMEM>>>();
  // 4) transpose+split w_o -> fp16 hi/lo
  k_splitT<<<dim3(HID/32, HID/32), 256>>>(w_o, HID);
  // 5) output projection (fp16 2-term) -> d_out
  k_gemm_o<<<dim3(HID/128, MTOT/128), 256, GO_SMEM>>>(out);
}

// round 17
// speedup vs baseline: 1.4291x; 1.0527x over previous
#include <cuda_runtime.h>
#include <cuda_bf16.h>
#include <cuda_fp16.h>
#include <cstdint>
#include <cstddef>

// Problem constants (fixed shapes).
#define BATCH 2
#define SEQ   2048
#define HID   2048
#define NH    16
#define HD    128
#define QKVN  (3*HID)   // 6144
#define MTOT  (BATCH*SEQ)

// Scratch (device globals; no allocations allowed). fp16 payloads in bf16-typed
// buffers (byte-compatible).
__device__ __nv_bfloat16 g_ahi[(size_t)MTOT*HID];        // fp16 A (x, later ctx)
__device__ __nv_bfloat16 g_alo[(size_t)MTOT*HID];        // (unused)
__device__ __nv_bfloat16 g_bhi[(size_t)QKVN*HID];        // fp16 weights^T hi [N][2048]
__device__ __nv_bfloat16 g_blo[(size_t)QKVN*HID];        // fp16 weights^T lo
__device__ __nv_bfloat16 g_qkvhi[(size_t)3*BATCH*NH*SEQ*HD];  // fp16: Qhi | K | V
__device__ __nv_bfloat16 g_qkvlo[(size_t)3*BATCH*NH*SEQ*HD];  // fp16: Qlo (which=0 only)

// ===========================================================================
// PTX helpers
// ===========================================================================
__device__ __forceinline__ unsigned smem_u32(const void* p) {
  unsigned a;
  asm("{ .reg .u64 t; cvta.to.shared.u64 t, %1; cvt.u32.u64 %0, t; }"
      : "=r"(a) : "l"(p));
  return a;
}
__device__ __forceinline__ void cp16(unsigned dst, const void* src) {
  asm volatile("cp.async.cg.shared.global [%0], [%1], 16;"
               :: "r"(dst), "l"(__cvta_generic_to_global(src)));
}
__device__ __forceinline__ void cp_commit() {
  asm volatile("cp.async.commit_group;" ::: "memory");
}
__device__ __forceinline__ void cp_wait0() {
  asm volatile("cp.async.wait_group 0;" ::: "memory");
}
__device__ __forceinline__ void cp_wait1() {
  asm volatile("cp.async.wait_group 1;" ::: "memory");
}
__device__ __forceinline__ void cp_wait3() {
  asm volatile("cp.async.wait_group 3;" ::: "memory");
}
__device__ __forceinline__ void ldsm4(unsigned* r, unsigned addr) {
  asm volatile("ldmatrix.sync.aligned.m8n8.x4.shared.b16 {%0,%1,%2,%3}, [%4];"
               : "=r"(r[0]), "=r"(r[1]), "=r"(r[2]), "=r"(r[3]) : "r"(addr));
}
__device__ __forceinline__ void ldsm4t(unsigned* r, unsigned addr) {
  asm volatile("ldmatrix.sync.aligned.m8n8.x4.trans.shared.b16 {%0,%1,%2,%3}, [%4];"
               : "=r"(r[0]), "=r"(r[1]), "=r"(r[2]), "=r"(r[3]) : "r"(addr));
}
__device__ __forceinline__ void mma_f16(float* d, const unsigned* a,
                                        const unsigned* b) {
  asm volatile(
    "mma.sync.aligned.m16n8k16.row.col.f32.f16.f16.f32 "
    "{%0,%1,%2,%3}, {%4,%5,%6,%7}, {%8,%9}, {%0,%1,%2,%3};"
    : "+f"(d[0]), "+f"(d[1]), "+f"(d[2]), "+f"(d[3])
    : "r"(a[0]), "r"(a[1]), "r"(a[2]), "r"(a[3]), "r"(b[0]), "r"(b[1]));
}
__device__ __forceinline__ unsigned packf16(float lo, float hi) {
  unsigned r;
  asm("cvt.rn.f16x2.f32 %0, %1, %2;" : "=r"(r) : "f"(hi), "f"(lo));
  return r;
}
__device__ __forceinline__ float f16lo(unsigned r) {
  __half2 h = *(__half2*)&r; return __low2float(h);
}
__device__ __forceinline__ float f16hi(unsigned r) {
  __half2 h = *(__half2*)&r; return __high2float(h);
}

// ===========================================================================
// fp32 -> fp16 convert (elementwise) into g_ahi (as __half)
// ===========================================================================
__global__ void __launch_bounds__(256) k_split(const float4* __restrict__ in,
                                               int n4)
{
  int i = blockIdx.x * 256 + threadIdx.x;
  if (i >= n4) return;
  float4 v = in[i];
  __half2* o = (__half2*)g_ahi;
  o[2*i]   = __floats2half2_rn(v.x, v.y);
  o[2*i+1] = __floats2half2_rn(v.z, v.w);
}

// ===========================================================================
// w [K=2048][N] fp32 -> transposed fp16 hi/lo [N][2048] into g_bhi/g_blo.
// Blo written only for n < nlo (columns whose GEMM runs 2-term).
// ===========================================================================
__global__ void __launch_bounds__(256) k_splitT(const float* __restrict__ w,
                                                int N, int nlo)
{
  __shared__ float t[32][33];
  const int n0 = blockIdx.x * 32, k0 = blockIdx.y * 32;
  const int tx = threadIdx.x & 31, ty = threadIdx.x >> 5;
#pragma unroll
  for (int i = 0; i < 4; ++i)
    t[ty + i*8][tx] = w[(size_t)(k0 + ty + i*8) * N + n0 + tx];
  __syncthreads();
#pragma unroll
  for (int i = 0; i < 4; ++i) {
    const int n = n0 + ty + i*8, k = k0 + tx;
    float v = t[tx][ty + i*8];
    __half h = __float2half_rn(v);
    ((__half*)g_bhi)[(size_t)n * HID + k] = h;
    if (n < nlo)
      ((__half*)g_blo)[(size_t)n * HID + k] = __float2half_rn(v - __half2float(h));
  }
}

// ===========================================================================
// QKV GEMM (mixed-term fp16): 64x128 CTA tile, 128 threads, KC=32, 3 CTAs/SM.
// Q columns (n0 < 2048): 2-term weights. K/V columns: 1-term (they are rounded
// to single fp16 in the epilogue anyway; the extra term is below storage noise).
// Epilogue: Q -> fp16 hi/lo (g_qkvhi/g_qkvlo), K/V -> single fp16 (g_qkvhi).
// ===========================================================================
#define KC 32
#define QA_MATB 5120u                // 64*80
#define QB_MATB 10240u               // 128*80
#define QSTG (QA_MATB + 2u*QB_MATB)  // 25600
#define GQ_SMEM (2u*QSTG)            // 51200

__global__ void __launch_bounds__(128, 3) k_gemm_qkv(const float* __restrict__ bias)
{
  extern __shared__ __align__(128) char smem[];
  const unsigned sbase = smem_u32(smem);
  const int tid  = threadIdx.x;
  const int lane = tid & 31, wid = tid >> 5;
  const int m0 = blockIdx.y * 64, n0 = blockIdx.x * 128;
  const int K = HID;
  const int NC = K / KC;            // 64
  const bool two_term = (n0 < 2048);   // CTA-uniform: Q columns only
  const __half* Af  = (const __half*)g_ahi;
  const __half* Bh  = (const __half*)g_bhi;
  const __half* Bl  = (const __half*)g_blo;

  auto load_chunk = [&](int c) {
    const unsigned st = sbase + (unsigned)(c & 1) * QSTG;
    const int koff = c * KC;
#pragma unroll
    for (int i = 0; i < 10; ++i) {
      const int q = tid + i * 128;     // 1280 16B segs (768 used if 1-term)
      if (q >= 768 && !two_term) continue;
      unsigned dstoff; const __half* src;
      if (q < 256) {                   // A: 64 rows x 4 segs
        const int row = q >> 2, seg = q & 3;
        dstoff = (unsigned)row * 80u + (unsigned)seg * 16u;
        src = Af + (size_t)(m0 + row) * K + koff + seg * 8;
      } else {                         // B hi/lo: 128 rows x 4 segs each
        const int qq = q - 256, mat = qq >> 9, idx = qq & 511;
        const int row = idx >> 2, seg = idx & 3;
        dstoff = QA_MATB + (unsigned)mat * QB_MATB
               + (unsigned)row * 80u + (unsigned)seg * 16u;
        src = (mat ? Bl : Bh) + (size_t)(n0 + row) * K + koff + seg * 8;
      }
      cp16(st + dstoff, src);
    }
  };

  const int wm = wid & 1, wn = wid >> 1;
  const unsigned aoff0 = (unsigned)(wm*32 + (lane & 15)) * 80u
                       + (unsigned)(lane >> 4) * 16u;
  const unsigned boff0 = QA_MATB
                       + (unsigned)(wn*64 + (lane & 7) + ((lane >> 4) << 3)) * 80u
                       + (unsigned)((lane >> 3) & 1) * 16u;

  float acc[2][8][4];
#pragma unroll
  for (int mi = 0; mi < 2; ++mi)
#pragma unroll
    for (int nt = 0; nt < 8; ++nt)
#pragma unroll
      for (int r = 0; r < 4; ++r) acc[mi][nt][r] = 0.f;

  load_chunk(0); cp_commit();

  for (int c = 0; c < NC; ++c) {
    if (c + 1 < NC) load_chunk(c + 1);
    cp_commit();
    cp_wait1();
    __syncthreads();

    const unsigned st = sbase + (unsigned)(c & 1) * QSTG;
#pragma unroll
    for (int ks = 0; ks < 2; ++ks) {
      unsigned ah[2][4];
#pragma unroll
      for (int mi = 0; mi < 2; ++mi)
        ldsm4(ah[mi], st + aoff0 + (unsigned)mi*1280u + (unsigned)ks*32u);
#pragma unroll
      for (int nj = 0; nj < 4; ++nj) {
        unsigned bh[4], bl[4];
        const unsigned b = st + boff0 + (unsigned)nj*1280u + (unsigned)ks*32u;
        ldsm4(bh, b);
        if (two_term) ldsm4(bl, b + QB_MATB);
#pragma unroll
        for (int mi = 0; mi < 2; ++mi)
#pragma unroll
          for (int hf = 0; hf < 2; ++hf) {
            float* a = acc[mi][nj*2 + hf];
            mma_f16(a, ah[mi], &bh[hf*2]);
            if (two_term) mma_f16(a, ah[mi], &bl[hf*2]);
          }
      }
    }
    __syncthreads();
  }

  // Epilogue: bias + store head-major q/k/v (Q fp16 hi/lo; K,V single fp16).
  __half* qkvh = (__half*)g_qkvhi;
  __half* qkvl = (__half*)g_qkvlo;
#pragma unroll
  for (int mi = 0; mi < 2; ++mi)
#pragma unroll
    for (int nt = 0; nt < 8; ++nt) {
      const int r0 = m0 + wm*32 + mi*16 + (lane >> 2);
      const int n  = n0 + wn*64 + nt*8 + (lane & 3)*2;
      const float2 bv = *(const float2*)&bias[n];
      const float p0 = acc[mi][nt][0] + bv.x, p1 = acc[mi][nt][1] + bv.y;
      const float p2 = acc[mi][nt][2] + bv.x, p3 = acc[mi][nt][3] + bv.y;
      const int which = n >> 11, hh = (n >> 7) & 15, dd = n & 127;
      const int bb = r0 >> 11, s = r0 & 2047;
      const size_t o0 = ((size_t)((which*BATCH + bb)*NH + hh) * SEQ + s) * HD + dd;
      const size_t o1 = o0 + 8*HD;
      const unsigned h0 = packf16(p0, p1);
      const unsigned h1 = packf16(p2, p3);
      *(unsigned*)&qkvh[o0] = h0;
      *(unsigned*)&qkvh[o1] = h1;
      if (which == 0) {
        const unsigned l0 = packf16(p0 - f16lo(h0), p1 - f16hi(h0));
        const unsigned l1 = packf16(p2 - f16lo(h1), p3 - f16hi(h1));
        *(unsigned*)&qkvl[o0] = l0;
        *(unsigned*)&qkvl[o1] = l1;
      }
    }
}

// ===========================================================================
// Proj GEMM (fp16 2-term): 128x128 CTA tile, 256 threads, 2 CTAs/SM.
// ===========================================================================
#define OA_MATB 10240u               // 128*80
#define OB_MATB 10240u
#define OSTG (OA_MATB + 2u*OB_MATB)  // 30720
#define GO_SMEM (2u*OSTG)            // 61440

__global__ void __launch_bounds__(256, 2) k_gemm_o(float* __restrict__ Carg)
{
  extern __shared__ __align__(128) char smem[];
  const unsigned sbase = smem_u32(smem);
  const int tid  = threadIdx.x;
  const int lane = tid & 31, wid = tid >> 5;
  const int m0 = blockIdx.y * 128, n0 = blockIdx.x * 128;
  const int K = HID, N = HID;
  const int NC = K / KC;            // 64
  const __half* Af  = (const __half*)g_ahi;
  const __half* Bh  = (const __half*)g_bhi;
  const __half* Bl  = (const __half*)g_blo;

  auto load_chunk = [&](int c) {
    const unsigned st = sbase + (unsigned)(c & 1) * OSTG;
    const int koff = c * KC;
#pragma unroll
    for (int i = 0; i < 6; ++i) {
      const int q = tid + i * 256;     // 1536 16B segs
      unsigned dstoff; const __half* src;
      if (q < 512) {                   // A: 128 rows x 4 segs
        const int row = q >> 2, seg = q & 3;
        dstoff = (unsigned)row * 80u + (unsigned)seg * 16u;
        src = Af + (size_t)(m0 + row) * K + koff + seg * 8;
      } else {                         // B hi/lo: 128 rows x 4 segs each
        const int qq = q - 512, mat = qq >> 9, idx = qq & 511;
        const int row = idx >> 2, seg = idx & 3;
        dstoff = OA_MATB + (unsigned)mat * OB_MATB
               + (unsigned)row * 80u + (unsigned)seg * 16u;
        src = (mat ? Bl : Bh) + (size_t)(n0 + row) * K + koff + seg * 8;
      }
      cp16(st + dstoff, src);
    }
  };

  const int wm = wid & 3, wn = wid >> 2;
  const unsigned aoff0 = (unsigned)(wm*32 + (lane & 15)) * 80u
                       + (unsigned)(lane >> 4) * 16u;
  const unsigned boff0 = OA_MATB
                       + (unsigned)(wn*64 + (lane & 7) + ((lane >> 4) << 3)) * 80u
                       + (unsigned)((lane >> 3) & 1) * 16u;

  float acc[2][8][4];
#pragma unroll
  for (int mi = 0; mi < 2; ++mi)
#pragma unroll
    for (int nt = 0; nt < 8; ++nt)
#pragma unroll
      for (int r = 0; r < 4; ++r) acc[mi][nt][r] = 0.f;

  load_chunk(0); cp_commit();

  for (int c = 0; c < NC; ++c) {
    if (c + 1 < NC) load_chunk(c + 1);
    cp_commit();
    cp_wait1();
    __syncthreads();

    const unsigned st = sbase + (unsigned)(c & 1) * OSTG;
#pragma unroll
    for (int ks = 0; ks < 2; ++ks) {
      unsigned ah[2][4];
#pragma unroll
      for (int mi = 0; mi < 2; ++mi)
        ldsm4(ah[mi], st + aoff0 + (unsigned)mi*1280u + (unsigned)ks*32u);
#pragma unroll
      for (int nj = 0; nj < 4; ++nj) {
        unsigned bh[4], bl[4];
        const unsigned b = st + boff0 + (unsigned)nj*1280u + (unsigned)ks*32u;
        ldsm4(bh, b);
        ldsm4(bl, b + OB_MATB);
#pragma unroll
        for (int mi = 0; mi < 2; ++mi)
#pragma unroll
          for (int hf = 0; hf < 2; ++hf) {
            float* a = acc[mi][nj*2 + hf];
            mma_f16(a, ah[mi], &bh[hf*2]);
            mma_f16(a, ah[mi], &bl[hf*2]);
          }
      }
    }
    __syncthreads();
  }

#pragma unroll
  for (int mi = 0; mi < 2; ++mi)
#pragma unroll
    for (int nt = 0; nt < 8; ++nt) {
      const int r0 = m0 + wm*32 + mi*16 + (lane >> 2);
      const int n  = n0 + wn*64 + nt*8 + (lane & 3)*2;
      *(float2*)&Carg[(size_t)r0 * N + n] =
          make_float2(acc[mi][nt][0], acc[mi][nt][1]);
      *(float2*)&Carg[(size_t)(r0 + 8) * N + n] =
          make_float2(acc[mi][nt][2], acc[mi][nt][3]);
    }
}

// ===========================================================================
// Pipelined fp16 flash attention (causal) — unchanged from R16.
// S = (Qhi+Qlo) * K (K single fp16); PV = (Phi+Plo) * V (V single fp16).
// ===========================================================================
#define AT_STR   272u                 // bytes per 128-col fp16 row (+pad)
#define AT_MATB  17408u               // 64*272  (one K or V matrix)
#define AT_KVST  (2u*AT_MATB)         // 34816   (K | V)
#define AT_QHI   (2u*AT_KVST)         // 69632
#define AT_QLO   (AT_QHI + 34816u)    // 104448
#define AT_SMEM  (AT_QLO + 34816u)    // 139264

__global__ void __launch_bounds__(256, 1) k_attn()
{
  extern __shared__ __align__(128) char smem[];
  const unsigned sb = smem_u32(smem);
  const int tid = threadIdx.x, lane = tid & 31, w = tid >> 5;
  const int qt = (int)gridDim.x - 1 - (int)blockIdx.x;   // heavy tiles first
  const int h = blockIdx.y, b = blockIdx.z;
  const int q0 = qt * 128;
  const int ktmax = 2*qt + 1;

  const __half* qkvh = (const __half*)g_qkvhi;
  const __half* qkvl = (const __half*)g_qkvlo;
  const size_t offQ = ((size_t)((0*BATCH + b)*NH + h)) * SEQ * HD;
  const size_t offK = ((size_t)((1*BATCH + b)*NH + h)) * SEQ * HD;
  const size_t offV = ((size_t)((2*BATCH + b)*NH + h)) * SEQ * HD;

  auto stage_k = [&](int kt) {
    const int k0 = kt * 64;
    const unsigned st = sb + (unsigned)(kt & 1) * AT_KVST;
#pragma unroll
    for (int i = 0; i < 4; ++i) {
      const int q = tid + i * 256;            // 1024 segs
      const int row = q >> 4, seg = q & 15;
      cp16(st + (unsigned)row * AT_STR + (unsigned)seg * 16u,
           qkvh + offK + (size_t)(k0 + row) * HD + seg * 8);
    }
  };
  auto stage_v = [&](int kt) {
    const int k0 = kt * 64;
    const unsigned st = sb + (unsigned)(kt & 1) * AT_KVST + AT_MATB;
#pragma unroll
    for (int i = 0; i < 4; ++i) {
      const int q = tid + i * 256;            // 1024 segs
      const int row = q >> 4, seg = q & 15;
      cp16(st + (unsigned)row * AT_STR + (unsigned)seg * 16u,
           qkvh + offV + (size_t)(k0 + row) * HD + seg * 8);
    }
  };

  // Stage Q (hi+lo) into persistent blocks.
#pragma unroll
  for (int i = 0; i < 16; ++i) {
    const int q = tid + i * 256;              // 4096 segs
    const int mat = q >> 11, row = (q >> 4) & 127, seg = q & 15;
    cp16(sb + (mat ? AT_QLO : AT_QHI)
            + (unsigned)row * AT_STR + (unsigned)seg * 16u,
         (mat ? qkvl : qkvh) + offQ + (size_t)(q0 + row) * HD + seg * 8);
  }
  cp_commit();                                // G: Q
  stage_k(0); cp_commit();                    // G: K0
  stage_v(0); cp_commit();                    // G: V0
  stage_k(1); cp_commit();                    // G: K1
  stage_v(1); cp_commit();                    // G: V1

  // ldmatrix per-lane offsets
  const unsigned aoff = (unsigned)(w*16 + (lane & 15)) * AT_STR
                      + (unsigned)(lane >> 4) * 16u;                 // Q rows
  const unsigned boff = (unsigned)((lane & 7) + ((lane >> 4) << 3)) * AT_STR
                      + (unsigned)((lane >> 3) & 1) * 16u;           // K cols
  const unsigned voff = (unsigned)(lane & 15) * AT_STR
                      + (unsigned)(lane >> 4) * 16u;                 // V (trans)

  auto compute_S = [&](unsigned stK, float S[8][4]) {
#pragma unroll
    for (int nb = 0; nb < 8; ++nb)
#pragma unroll
      for (int r = 0; r < 4; ++r) S[nb][r] = 0.f;
#pragma unroll
    for (int kc = 0; kc < 8; ++kc) {
      unsigned qhr[4], qlr[4];
      ldsm4(qhr, sb + AT_QHI + aoff + (unsigned)kc*32u);
      ldsm4(qlr, sb + AT_QLO + aoff + (unsigned)kc*32u);
#pragma unroll
      for (int j = 0; j < 4; ++j) {
        unsigned kf[4];
        ldsm4(kf, stK + boff + (unsigned)j*4352u + (unsigned)kc*32u);
        mma_f16(S[2*j],   qhr, &kf[0]);  mma_f16(S[2*j+1], qhr, &kf[2]);
        mma_f16(S[2*j],   qlr, &kf[0]);  mma_f16(S[2*j+1], qlr, &kf[2]);
      }
    }
  };

  const float sc = 0.08838834764831845f;   // 1/sqrt(128)
  float m0r = -1e30f, m1r = -1e30f, l0 = 0.f, l1 = 0.f;
  float O[16][4];
#pragma unroll
  for (int nb = 0; nb < 16; ++nb)
#pragma unroll
    for (int r = 0; r < 4; ++r) O[nb][r] = 0.f;

  const int wrow = q0 + w*16;              // warp's first q row

  // Pre-loop: wait {Q, K0}; compute S_0.
  cp_wait3();
  __syncthreads();
  float Scur[8][4];
  compute_S(sb, Scur);

  for (int kt = 0; kt <= ktmax; ++kt) {
    if (kt == ktmax) cp_wait0(); else cp_wait1();
    __syncthreads();

    if (kt + 2 <= ktmax) stage_k(kt + 2);
    cp_commit();

    float Snext[8][4];
    const bool have_next = (kt < ktmax) && ((kt + 1) * 64 <= wrow + 15);
    if (have_next)
      compute_S(sb + (unsigned)((kt + 1) & 1) * AT_KVST, Snext);

    const int k0 = kt * 64;
    const unsigned st = sb + (unsigned)(kt & 1) * AT_KVST;
    if (k0 <= wrow + 15) {
      if (k0 + 63 > wrow) {
        const int rl0 = wrow + (lane >> 2), rl1 = rl0 + 8;
#pragma unroll
        for (int nb = 0; nb < 8; ++nb) {
          const int c0 = k0 + nb*8 + 2*(lane & 3), c1 = c0 + 1;
          if (c0 > rl0) Scur[nb][0] = -1e30f;
          if (c1 > rl0) Scur[nb][1] = -1e30f;
          if (c0 > rl1) Scur[nb][2] = -1e30f;
          if (c1 > rl1) Scur[nb][3] = -1e30f;
        }
      }

      float mx0 = -1e30f, mx1 = -1e30f;
#pragma unroll
      for (int nb = 0; nb < 8; ++nb) {
        mx0 = fmaxf(mx0, fmaxf(Scur[nb][0], Scur[nb][1]));
        mx1 = fmaxf(mx1, fmaxf(Scur[nb][2], Scur[nb][3]));
      }
      mx0 = fmaxf(mx0, __shfl_xor_sync(0xFFFFFFFFu, mx0, 1));
      mx0 = fmaxf(mx0, __shfl_xor_sync(0xFFFFFFFFu, mx0, 2));
      mx1 = fmaxf(mx1, __shfl_xor_sync(0xFFFFFFFFu, mx1, 1));
      mx1 = fmaxf(mx1, __shfl_xor_sync(0xFFFFFFFFu, mx1, 2));
      const float mn0 = fmaxf(m0r, mx0), mn1 = fmaxf(m1r, mx1);
      const float a0 = __expf(sc * (m0r - mn0));
      const float a1 = __expf(sc * (m1r - mn1));
      m0r = mn0; m1r = mn1;

      float ls0 = 0.f, ls1 = 0.f;
#pragma unroll
      for (int nb = 0; nb < 8; ++nb) {
        Scur[nb][0] = __expf(sc * (Scur[nb][0] - mn0));
        Scur[nb][1] = __expf(sc * (Scur[nb][1] - mn0));
        Scur[nb][2] = __expf(sc * (Scur[nb][2] - mn1));
        Scur[nb][3] = __expf(sc * (Scur[nb][3] - mn1));
        ls0 += Scur[nb][0] + Scur[nb][1];
        ls1 += Scur[nb][2] + Scur[nb][3];
      }
      l0 = l0 * a0 + ls0;
      l1 = l1 * a1 + ls1;

#pragma unroll
      for (int nb = 0; nb < 16; ++nb) {
        O[nb][0] *= a0; O[nb][1] *= a0;
        O[nb][2] *= a1; O[nb][3] *= a1;
      }

      // ---- P hi/lo fp16 fragments ----
      unsigned ph[4][4], pl[4][4];
#pragma unroll
      for (int kc2 = 0; kc2 < 4; ++kc2) {
        const float* p0 = Scur[2*kc2];
        const float* p1 = Scur[2*kc2+1];
        ph[kc2][0] = packf16(p0[0], p0[1]);
        ph[kc2][1] = packf16(p0[2], p0[3]);
        ph[kc2][2] = packf16(p1[0], p1[1]);
        ph[kc2][3] = packf16(p1[2], p1[3]);
        pl[kc2][0] = packf16(p0[0] - f16lo(ph[kc2][0]), p0[1] - f16hi(ph[kc2][0]));
        pl[kc2][1] = packf16(p0[2] - f16lo(ph[kc2][1]), p0[3] - f16hi(ph[kc2][1]));
        pl[kc2][2] = packf16(p1[0] - f16lo(ph[kc2][2]), p1[1] - f16hi(ph[kc2][2]));
        pl[kc2][3] = packf16(p1[2] - f16lo(ph[kc2][3]), p1[3] - f16hi(ph[kc2][3]));
      }

      // ---- O += (Phi+Plo) V (V single fp16), 16x128 ----
#pragma unroll
      for (int kc2 = 0; kc2 < 4; ++kc2) {
#pragma unroll
        for (int j = 0; j < 8; ++j) {
          unsigned vf[4];
          ldsm4t(vf, st + AT_MATB + voff + (unsigned)kc2*4352u + (unsigned)j*32u);
          mma_f16(O[2*j],   ph[kc2], &vf[0]);  mma_f16(O[2*j+1], ph[kc2], &vf[2]);
          mma_f16(O[2*j],   pl[kc2], &vf[0]);  mma_f16(O[2*j+1], pl[kc2], &vf[2]);
        }
      }
    }

    __syncthreads();       // all warps done with V(kt) before restage
    if (kt + 2 <= ktmax) stage_v(kt + 2);
    cp_commit();

    if (have_next) {
#pragma unroll
      for (int nb = 0; nb < 8; ++nb)
#pragma unroll
        for (int r = 0; r < 4; ++r) Scur[nb][r] = Snext[nb][r];
    }
  }

  // ---- finalize: normalize, write ctx as single fp16 into g_ahi ----
  l0 += __shfl_xor_sync(0xFFFFFFFFu, l0, 1);
  l0 += __shfl_xor_sync(0xFFFFFFFFu, l0, 2);
  l1 += __shfl_xor_sync(0xFFFFFFFFu, l1, 1);
  l1 += __shfl_xor_sync(0xFFFFFFFFu, l1, 2);
  const float inv0 = 1.f / l0, inv1 = 1.f / l1;

  __half* ctx = (__half*)g_ahi;
  const int s0 = q0 + w*16 + (lane >> 2), s1 = s0 + 8;
  const size_t rb0 = ((size_t)b*SEQ + s0) * HID + h*HD;
  const size_t rb1 = ((size_t)b*SEQ + s1) * HID + h*HD;
#pragma unroll
  for (int nb = 0; nb < 16; ++nb) {
    const int c = nb*8 + 2*(lane & 3);
    const unsigned f0 = packf16(O[nb][0]*inv0, O[nb][1]*inv0);
    const unsigned f1 = packf16(O[nb][2]*inv1, O[nb][3]*inv1);
    *(unsigned*)&ctx[rb0 + c] = f0;
    *(unsigned*)&ctx[rb1 + c] = f1;
  }
}

// ---------------------------------------------------------------------------
extern "C" void kernel_launch(void* const* d_in, const int* in_sizes, int n_in,
                              void* d_out, int out_size)
{
  const float* x     = (const float*)d_in[0];
  const float* w_qkv = (const float*)d_in[1];
  const float* b_qkv = (const float*)d_in[2];
  const float* w_o   = (const float*)d_in[3];
  float* out = (float*)d_out;

  cudaFuncSetAttribute(k_gemm_qkv, cudaFuncAttributeMaxDynamicSharedMemorySize, GQ_SMEM);
  cudaFuncSetAttribute(k_gemm_o,   cudaFuncAttributeMaxDynamicSharedMemorySize, GO_SMEM);
  cudaFuncSetAttribute(k_attn,     cudaFuncAttributeMaxDynamicSharedMemorySize, AT_SMEM);

  const int n4x = MTOT*HID/4;   // 2,097,152

  // 1) convert x -> fp16; transpose+split w_qkv (lo only for Q columns)
  k_split<<<(n4x + 255)/256, 256>>>((const float4*)x, n4x);
  k_splitT<<<dim3(QKVN/32, HID/32), 256>>>(w_qkv, QKVN, 2048);
  // 2) QKV GEMM (Q: fp16 2-term; K/V: 1-term) -> head-major fp16
  k_gemm_qkv<<<dim3(QKVN/128, MTOT/64), 128, GQ_SMEM>>>(b_qkv);
  // 3) fp16 flash attention (2-term S, 2-term PV) -> ctx fp16 into g_ahi
  k_attn<<<dim3(SEQ/128, NH, BATCH), 256, AT_SMEM>>>();
  // 4) transpose+split w_o -> fp16 hi/lo (all columns 2-term)
  k_splitT<<<dim3(HID/32, HID/32), 256>>>(w_o, HID, HID);
  // 5) output projection (fp16 2-term) -> d_out
  k_gemm_o<<<dim3(HID/128, MTOT/128), 256, GO_SMEM>>>(out);
}